// round 7
// baseline (speedup 1.0000x reference)
#include <cuda_runtime.h>
#include <cuda_bf16.h>
#include <math.h>
#include <stdint.h>

// ---------------- constants ----------------
#define BB   16
#define NN_  512
#define LL   1024
#define CD   128
#define GD   64
#define NH   4
#define LAT  128

// ---------------- scratch ----------------
__device__ float g_av       [BB*NN_*CD];
__device__ float g_wh1      [BB*NN_*(GD*NH)];
__device__ float g_multi    [BB*NN_*(GD*NH)];
__device__ float g_wh2      [BB*NN_*CD];
__device__ float g_x        [BB*NN_*CD];
__device__ float g_atoms_vec[BB*NN_*LAT];
__device__ float g_av_att   [BB*NN_*LAT];
__device__ float g_src1[BB*NH*NN_], g_dst1[BB*NH*NN_];
__device__ float g_src2[BB*NN_],    g_dst2[BB*NN_];
__device__ float g_cnvA[BB*LL*CD];
__device__ float g_cnvB[BB*LL*CD];
__device__ float g_T[30*11*CD];
__device__ float g_WcatT[256*128];     // [n=h*64+f][k]
__device__ float g_WgoT [128*256];     // [n][k]
__device__ float g_comp[BB*LAT], g_prot[BB*LAT];
__device__ float g_pp[BB*8*128];
__device__ float g_pm[BB*8];
__device__ uint32_t g_adjmask[BB*NN_*16];

__device__ __forceinline__ float lrelu(float x){ return x > 0.f ? x : 0.2f*x; }
__device__ __forceinline__ float eluf (float x){ return x > 0.f ? x : (__expf(x) - 1.f); }

// ---------------- f32x2 packed helpers (conv only) ----------------
__device__ __forceinline__ uint64_t pk2(float x){
    uint32_t xi = __float_as_uint(x);
    uint64_t r; asm("mov.b64 %0, {%1, %1};" : "=l"(r) : "r"(xi)); return r;
}
__device__ __forceinline__ uint64_t pk2f(float x, float y){
    uint32_t xi = __float_as_uint(x), yi = __float_as_uint(y);
    uint64_t r; asm("mov.b64 %0, {%1, %2};" : "=l"(r) : "r"(xi), "r"(yi)); return r;
}
__device__ __forceinline__ void fma2(uint64_t& d, uint64_t a, uint64_t b){
    asm("fma.rn.f32x2 %0, %1, %2, %0;" : "+l"(d) : "l"(a), "l"(b));
}
__device__ __forceinline__ float2 up2(uint64_t v){
    uint32_t lo, hi; asm("mov.b64 {%0, %1}, %2;" : "=r"(lo), "=r"(hi) : "l"(v));
    return make_float2(__uint_as_float(lo), __uint_as_float(hi));
}

// ---------------- bf16 split helpers ----------------
__device__ __forceinline__ void split2(float x, float y, uint32_t& hi, uint32_t& lo){
    __nv_bfloat162 h = __floats2bfloat162_rn(x, y);
    float hx = __bfloat162float(h.x), hy = __bfloat162float(h.y);
    __nv_bfloat162 l = __floats2bfloat162_rn(x - hx, y - hy);
    hi = *(uint32_t*)&h; lo = *(uint32_t*)&l;
}
__device__ __forceinline__ void split1(float x, __nv_bfloat16& h, __nv_bfloat16& l){
    h = __float2bfloat16(x);
    l = __float2bfloat16(x - __bfloat162float(h));
}

// mma.sync m16n8k16 bf16 (sm_80+)
__device__ __forceinline__ void mma16816(float* d, const uint32_t* a, const uint32_t* b){
    asm volatile(
        "mma.sync.aligned.m16n8k16.row.col.f32.bf16.bf16.f32 "
        "{%0,%1,%2,%3},{%4,%5,%6,%7},{%8,%9},{%0,%1,%2,%3};"
        : "+f"(d[0]), "+f"(d[1]), "+f"(d[2]), "+f"(d[3])
        : "r"(a[0]), "r"(a[1]), "r"(a[2]), "r"(a[3]), "r"(b[0]), "r"(b[1]));
}

// ---------------- fused prep kernel ----------------
// [0,16384) packadj | [16384,16512) wgatT | [16512,16640) goT
// [16640,16805) table | [16805,20901) embed
__global__ void __launch_bounds__(256) k_prep(
    const int* __restrict__ adj, const float* __restrict__ W_gat,
    const float* __restrict__ W_go, const float* __restrict__ conv_w,
    const float* __restrict__ E_amino, const int* __restrict__ atoms,
    const float* __restrict__ E_atom)
{
    const int bid = blockIdx.x, tid = threadIdx.x;
    if (bid < 16384) {
        int t = bid*256 + tid;
        uint32_t bal = __ballot_sync(0xffffffffu, adj[t] > 0);
        if ((t & 31) == 0) g_adjmask[t >> 5] = bal;
    } else if (bid < 16512) {
        int idx = (bid - 16384)*256 + tid;
        int n = idx >> 7, k = idx & 127;
        int h = n >> 6, f = n & 63;
        g_WcatT[n*128 + k] = W_gat[((h*128) + k)*64 + f];
    } else if (bid < 16640) {
        int idx = (bid - 16512)*256 + tid;
        int n = idx >> 8, k = idx & 255;
        g_WgoT[n*256 + k] = W_go[k*128 + n];
    } else if (bid < 16805) {
        int idx = (bid - 16640)*256 + tid;
        if (idx < 42240) {
            int f = idx & 127, rest = idx >> 7;
            int dl = rest % 11, a = rest / 11;
            float acc = 0.f;
            #pragma unroll
            for (int df = 0; df < 11; ++df) {
                int fi = f + df - 5;
                if (fi >= 0 && fi < 128) acc += conv_w[dl*11 + df] * E_amino[a*128 + fi];
            }
            g_T[(a*11 + dl)*128 + f] = acc;
        }
    } else {
        int idx = (bid - 16805)*256 + tid;
        int row = idx >> 7, f = idx & 127;
        g_av[(size_t)row*128 + f] = E_atom[atoms[row]*128 + f];
    }
}

// ---------------- bf16-split tensor GEMM: C = act(A @ BT^T + bias) ----------------
// tile 64m x 64n, 8 warps (wm 4 x wn 2), static smem 36KB
template<int ACT>
__global__ void __launch_bounds__(256) k_mm(
    const float* __restrict__ A, const float* __restrict__ BT,
    const float* __restrict__ bias, float* __restrict__ C,
    int M, int N, int K)
{
    __shared__ uint32_t Ah[2304], Al[2304], Bh[2304], Bl[2304];  // 64*36 words

    const int m0 = blockIdx.x*64, n0 = blockIdx.y*64;
    const int tid = threadIdx.x, w = tid >> 5, lane = tid & 31;
    const int wm = w & 3, wn = w >> 2;
    const int r4 = lane >> 2, cl = lane & 3;

    float acc[4][4];
    #pragma unroll
    for (int j = 0; j < 4; ++j)
        #pragma unroll
        for (int q = 0; q < 4; ++q) acc[j][q] = 0.f;

    for (int k0 = 0; k0 < K; k0 += 64) {
        __syncthreads();
        #pragma unroll
        for (int s = tid; s < 1024; s += 256) {
            int r = s >> 4, q = s & 15;
            float4 v = *(const float4*)&A[(size_t)(m0+r)*K + k0 + q*4];
            uint32_t h0,l0,h1,l1;
            split2(v.x, v.y, h0, l0); split2(v.z, v.w, h1, l1);
            int off = r*36 + q*2;
            Ah[off] = h0; Ah[off+1] = h1;
            Al[off] = l0; Al[off+1] = l1;
            float4 bv = *(const float4*)&BT[(size_t)(n0+r)*K + k0 + q*4];
            split2(bv.x, bv.y, h0, l0); split2(bv.z, bv.w, h1, l1);
            Bh[off] = h0; Bh[off+1] = h1;
            Bl[off] = l0; Bl[off+1] = l1;
        }
        __syncthreads();
        #pragma unroll
        for (int kk = 0; kk < 4; ++kk) {
            const int kw = kk*8;
            uint32_t ah[4], al[4];
            {
                int base = (wm*16 + r4)*36 + kw + cl;
                ah[0]=Ah[base];     ah[1]=Ah[base+288];
                ah[2]=Ah[base+4];   ah[3]=Ah[base+292];
                al[0]=Al[base];     al[1]=Al[base+288];
                al[2]=Al[base+4];   al[3]=Al[base+292];
            }
            uint32_t bh[4][2], bl[4][2];
            #pragma unroll
            for (int fn = 0; fn < 4; ++fn) {
                int base = (wn*32 + fn*8 + r4)*36 + kw + cl;
                bh[fn][0]=Bh[base]; bh[fn][1]=Bh[base+4];
                bl[fn][0]=Bl[base]; bl[fn][1]=Bl[base+4];
            }
            #pragma unroll
            for (int fn = 0; fn < 4; ++fn) {
                mma16816(acc[fn], ah, bh[fn]);
                mma16816(acc[fn], ah, bl[fn]);
                mma16816(acc[fn], al, bh[fn]);
            }
        }
    }
    #pragma unroll
    for (int fn = 0; fn < 4; ++fn) {
        int row = m0 + wm*16 + r4;
        int col = n0 + wn*32 + fn*8 + 2*cl;
        float b0 = 0.f, b1 = 0.f;
        if (bias) { b0 = bias[col]; b1 = bias[col+1]; }
        float v0 = acc[fn][0] + b0, v1 = acc[fn][1] + b1;
        float v2 = acc[fn][2] + b0, v3 = acc[fn][3] + b1;
        if (ACT) { v0=lrelu(v0); v1=lrelu(v1); v2=lrelu(v2); v3=lrelu(v3); }
        *(float2*)&C[(size_t)row*N + col]     = make_float2(v0, v1);
        *(float2*)&C[(size_t)(row+8)*N + col] = make_float2(v2, v3);
    }
}

// ---------------- unified GAT attention (64-row i-tile, 64-col f-tile) ----------------
// MH=1: multi-head layer (grid.y = head, WS=256); MH=0: single head, grid.y = f-split (WS=128)
template<int MH>
__global__ void __launch_bounds__(256) k_attn(
    const float* __restrict__ wh, const float* __restrict__ src,
    const float* __restrict__ dst, const uint32_t* __restrict__ adjmask,
    float* __restrict__ out, int WS)
{
    __shared__ float Df[512], Pf[512], Qf[512];
    __shared__ float sS[64], sP[64], sQ[64], Sum[64], pst[256];
    __shared__ uint32_t msk[1024];
    __shared__ uint32_t Ath[1152], Atl[1152];   // 64 rows * 18 words
    __shared__ uint32_t Bh[1152],  Bl[1152];    // 64 f    * 18 words

    const int it = blockIdx.x, hy = blockIdx.y, b = blockIdx.z;
    const int i0 = it*64;
    const int tid = threadIdx.x, w = tid >> 5, lane = tid & 31;
    const int r4 = lane >> 2, cl = lane & 3;
    const int whoff = hy*64;
    const int sdoff = MH ? (b*NH + hy) : b;

    const float* dstb = dst + (size_t)sdoff*512;
    const float* srcb = src + (size_t)sdoff*512;
    for (int j = tid; j < 512; j += 256) {
        float d = dstb[j];
        Df[j] = d; Pf[j] = __expf(d); Qf[j] = __expf(0.2f*d);
    }
    if (tid < 64) {
        float s = srcb[i0 + tid];
        sS[tid] = s; sP[tid] = __expf(s); sQ[tid] = __expf(0.2f*s);
    }
    {
        const uint32_t* mb = adjmask + ((size_t)(b*512) + i0)*16;
        for (int s = tid; s < 1024; s += 256) msk[s] = mb[s];
    }

    const int wm = w & 3, wn = w >> 2;
    float acc[4][4];
    #pragma unroll
    for (int j = 0; j < 4; ++j)
        #pragma unroll
        for (int q = 0; q < 4; ++q) acc[j][q] = 0.f;

    const int ai = tid >> 2, qt = tid & 3;      // row, j-quarter (8 j's)
    __syncthreads();
    const float si = sS[ai], pie = sP[ai], qie = sQ[ai];
    float ps = 0.f;

    for (int c = 0; c < 16; ++c) {
        const int j0 = c*32;
        if (c) __syncthreads();
        // --- A tile (64 x 32) hi/lo ---
        {
            uint32_t mw = msk[ai*16 + c];
            #pragma unroll
            for (int jp = 0; jp < 4; ++jp) {
                int jl0 = qt*8 + jp*2, jl1 = jl0 + 1;
                float v0 = 0.f, v1 = 0.f;
                if ((mw >> jl0) & 1u) {
                    int j = j0 + jl0;
                    v0 = (si + Df[j] > 0.f) ? pie*Pf[j] : qie*Qf[j];
                }
                if ((mw >> jl1) & 1u) {
                    int j = j0 + jl1;
                    v1 = (si + Df[j] > 0.f) ? pie*Pf[j] : qie*Qf[j];
                }
                ps += v0 + v1;
                uint32_t hw, lw; split2(v0, v1, hw, lw);
                int off = ai*18 + qt*4 + jp;
                Ath[off] = hw; Atl[off] = lw;
            }
        }
        // --- B tile: WhT [64 f x 32 j] hi/lo, transposed scalar stores ---
        {
            __nv_bfloat16* Bhb = (__nv_bfloat16*)Bh;
            __nv_bfloat16* Blb = (__nv_bfloat16*)Bl;
            const int f = tid & 63, jg = tid >> 6;
            #pragma unroll
            for (int jj = 0; jj < 8; ++jj) {
                int jl = jg*8 + jj;
                float v = wh[(size_t)(b*512 + j0 + jl)*WS + whoff + f];
                __nv_bfloat16 hv, lv; split1(v, hv, lv);
                Bhb[f*36 + jl] = hv; Blb[f*36 + jl] = lv;
            }
        }
        __syncthreads();
        // --- MMA: 2 k-steps of 16 ---
        #pragma unroll
        for (int kk = 0; kk < 2; ++kk) {
            const int kw = kk*8;
            uint32_t ah[4], al[4];
            {
                int base = (wm*16 + r4)*18 + kw + cl;
                ah[0]=Ath[base];     ah[1]=Ath[base+144];
                ah[2]=Ath[base+4];   ah[3]=Ath[base+148];
                al[0]=Atl[base];     al[1]=Atl[base+144];
                al[2]=Atl[base+4];   al[3]=Atl[base+148];
            }
            uint32_t bh[4][2], bl[4][2];
            #pragma unroll
            for (int fn = 0; fn < 4; ++fn) {
                int base = (wn*32 + fn*8 + r4)*18 + kw + cl;
                bh[fn][0]=Bh[base]; bh[fn][1]=Bh[base+4];
                bl[fn][0]=Bl[base]; bl[fn][1]=Bl[base+4];
            }
            #pragma unroll
            for (int fn = 0; fn < 4; ++fn) {
                mma16816(acc[fn], ah, bh[fn]);
                mma16816(acc[fn], ah, bl[fn]);
                mma16816(acc[fn], al, bh[fn]);
            }
        }
    }
    pst[tid] = ps;
    __syncthreads();
    if (tid < 64) Sum[tid] = pst[4*tid] + pst[4*tid+1] + pst[4*tid+2] + pst[4*tid+3];
    __syncthreads();
    // --- epilogue: normalize + elu ---
    {
        int rl = wm*16 + r4;
        float S0 = Sum[rl],   i0v = (S0 > 0.f) ? 1.f/S0 : 0.f;
        float S1 = Sum[rl+8], i1v = (S1 > 0.f) ? 1.f/S1 : 0.f;
        #pragma unroll
        for (int fn = 0; fn < 4; ++fn) {
            int col = whoff + wn*32 + fn*8 + 2*cl;
            float v0 = eluf(acc[fn][0] * i0v);
            float v1 = eluf(acc[fn][1] * i0v);
            float v2 = eluf(acc[fn][2] * i1v);
            float v3 = eluf(acc[fn][3] * i1v);
            *(float2*)&out[(size_t)(b*512 + i0 + rl)*WS + col]     = make_float2(v0, v1);
            *(float2*)&out[(size_t)(b*512 + i0 + rl + 8)*WS + col] = make_float2(v2, v3);
        }
    }
}

// ---------------- src/dst score kernels ----------------
__global__ void k_srcdst1(const float* __restrict__ a_gat){
    const int row = blockIdx.x;
    const int b = row >> 9, n = row & 511;
    const int tid = threadIdx.x;
    __shared__ float wrow[256];
    wrow[tid] = g_wh1[(size_t)row*256 + tid];
    __syncthreads();
    const int w = tid >> 5, l = tid & 31;
    const int h = w >> 1, half = w & 1;
    float v = wrow[h*64 + l]      * a_gat[h*128 + half*64 + l]
            + wrow[h*64 + 32 + l] * a_gat[h*128 + half*64 + 32 + l];
    #pragma unroll
    for (int o = 16; o; o >>= 1) v += __shfl_down_sync(0xffffffffu, v, o);
    if (l == 0) {
        float* outp = half ? g_dst1 : g_src1;
        outp[(size_t)(b*4 + h)*512 + n] = v;
    }
}
__global__ void k_srcdst2(const float* __restrict__ a_go){
    const int row = blockIdx.x;
    const int tid = threadIdx.x;
    __shared__ float wrow[128];
    __shared__ float part[4];
    wrow[tid] = g_wh2[(size_t)row*128 + tid];
    __syncthreads();
    const int w = tid >> 5, l = tid & 31;
    const int which = w >> 1, p = w & 1;
    float v = wrow[p*64 + l]      * a_go[which*128 + p*64 + l]
            + wrow[p*64 + 32 + l] * a_go[which*128 + p*64 + 32 + l];
    #pragma unroll
    for (int o = 16; o; o >>= 1) v += __shfl_down_sync(0xffffffffu, v, o);
    if (l == 0) part[w] = v;
    __syncthreads();
    if (tid == 0) g_src2[row] = part[0] + part[1];
    if (tid == 1) g_dst2[row] = part[2] + part[3];
}

// ---------------- CNN ----------------
__global__ void k_conv1(const int* __restrict__ amino, const float* __restrict__ conv_b){
    const int l = blockIdx.x, b = blockIdx.y, f = threadIdx.x;
    float acc = conv_b[0];
    #pragma unroll
    for (int dl = 0; dl < 11; ++dl) {
        int l2 = l + dl - 5;
        if (l2 >= 0 && l2 < 1024) {
            int id = amino[b*1024 + l2];
            acc += g_T[((size_t)id*11 + dl)*128 + f];
        }
    }
    g_cnvA[((size_t)(b*1024) + l)*128 + f] = fmaxf(acc, 0.f);
}
__global__ void __launch_bounds__(256) k_conv(
    const float* __restrict__ in, float* __restrict__ out,
    const float* __restrict__ wsrc, const float* __restrict__ bsrc)
{
    __shared__ float tile[26*139];
    __shared__ float ws[121];
    const int lb = blockIdx.x * 16, b = blockIdx.y;
    const int tid = threadIdx.x;
    if (tid < 121) ws[tid] = wsrc[tid];
    for (int idx = tid; idx < 26*138; idx += 256) {
        const int r = idx / 138, c = idx % 138;
        const int gl = lb + r - 5, gf = c - 5;
        float v = 0.f;
        if (gl >= 0 && gl < 1024 && gf >= 0 && gf < 128)
            v = in[((size_t)(b*1024) + gl)*128 + gf];
        tile[r*139 + c] = v;
    }
    __syncthreads();
    const int fg = tid >> 3, lg = tid & 7;
    const int f0 = fg * 4;
    uint64_t accp[4];
    {
        uint64_t bp = pk2(bsrc[0]);
        accp[0]=bp; accp[1]=bp; accp[2]=bp; accp[3]=bp;
    }
    for (int dl = 0; dl < 11; ++dl) {
        const float* w  = ws + dl*11;
        const float* r0 = tile + (lg + dl)*139 + f0;
        const float* r1 = r0 + 8*139;
        uint64_t vp[14];
        #pragma unroll
        for (int j = 0; j < 14; ++j) vp[j] = pk2f(r0[j], r1[j]);
        #pragma unroll
        for (int df = 0; df < 11; ++df) {
            uint64_t wv = pk2(w[df]);
            fma2(accp[0], wv, vp[df+0]);
            fma2(accp[1], wv, vp[df+1]);
            fma2(accp[2], wv, vp[df+2]);
            fma2(accp[3], wv, vp[df+3]);
        }
    }
    float* o0 = out + ((size_t)(b*1024) + lb + lg)*128 + f0;
    float* o1 = o0 + 8*128;
    #pragma unroll
    for (int k = 0; k < 4; ++k) {
        float2 v = up2(accp[k]);
        o0[k] = fmaxf(v.x, 0.f);
        o1[k] = fmaxf(v.y, 0.f);
    }
}

// ---------------- masked mean pooling ----------------
__global__ void k_mean_part(const float* __restrict__ in, const float* __restrict__ mask,
                            int NNd){
    const int ch = blockIdx.x, b = blockIdx.y, f = threadIdx.x;
    const int rows = NNd / 8;
    const int r0 = ch * rows;
    float s = 0.f, m = 0.f;
    #pragma unroll 4
    for (int n = r0; n < r0 + rows; ++n) {
        float mk = mask[b*NNd + n];
        m += mk;
        s += mk * in[((size_t)b*NNd + n)*128 + f];
    }
    g_pp[(size_t)(b*8 + ch)*128 + f] = s;
    if (f == 0) g_pm[b*8 + ch] = m;
}
__global__ void k_mean_fin(float* __restrict__ outp){
    const int b = blockIdx.x, f = threadIdx.x;
    float s = 0.f, m = 0.f;
    #pragma unroll
    for (int ch = 0; ch < 8; ++ch) {
        s += g_pp[(size_t)(b*8 + ch)*128 + f];
        m += g_pm[b*8 + ch];
    }
    outp[b*128 + f] = s / m;
}

// ---------------- final predictor ----------------
__global__ void k_final(const float* __restrict__ pred_w, const float* __restrict__ pred_b,
                        float* __restrict__ out){
    __shared__ float red[256];
    const int b = blockIdx.x, c = threadIdx.x;
    float v = (c < 128) ? g_comp[b*128 + c] : g_prot[b*128 + (c - 128)];
    v = v > 0.f ? v : 0.04f*v;
    red[c] = v * pred_w[c];
    __syncthreads();
    for (int s = 128; s > 0; s >>= 1) {
        if (c < s) red[c] += red[c + s];
        __syncthreads();
    }
    if (c == 0) out[b] = red[0] + pred_b[0];
}

// ---------------- launch ----------------
extern "C" void kernel_launch(void* const* d_in, const int* in_sizes, int n_in,
                              void* d_out, int out_size)
{
    const int*   atoms      = (const int*)  d_in[0];
    const float* atoms_mask = (const float*)d_in[1];
    const int*   adj        = (const int*)  d_in[2];
    const int*   amino      = (const int*)  d_in[3];
    const float* amino_mask = (const float*)d_in[4];
    const float* E_atom     = (const float*)d_in[5];
    const float* E_amino    = (const float*)d_in[6];
    const float* W_gat      = (const float*)d_in[7];
    const float* a_gat      = (const float*)d_in[8];
    const float* W_go       = (const float*)d_in[9];
    const float* a_go       = (const float*)d_in[10];
    const float* W_comp_w   = (const float*)d_in[11];
    const float* W_comp_b   = (const float*)d_in[12];
    const float* conv_w     = (const float*)d_in[13];
    const float* conv_b     = (const float*)d_in[14];
    const float* W_att_w    = (const float*)d_in[15];
    const float* W_att_b    = (const float*)d_in[16];
    const float* pred_w     = (const float*)d_in[17];
    const float* pred_b     = (const float*)d_in[18];
    float* out = (float*)d_out;

    float *p_WcatT, *p_WgoT;
    float *p_av, *p_wh1, *p_multi, *p_wh2, *p_x, *p_atoms_vec, *p_av_att;
    float *p_src1, *p_dst1, *p_src2, *p_dst2, *p_cnvA, *p_cnvB, *p_comp, *p_prot;
    uint32_t* p_adjm;
    cudaGetSymbolAddress((void**)&p_WcatT, g_WcatT);
    cudaGetSymbolAddress((void**)&p_WgoT,  g_WgoT);
    cudaGetSymbolAddress((void**)&p_av,    g_av);
    cudaGetSymbolAddress((void**)&p_wh1,   g_wh1);
    cudaGetSymbolAddress((void**)&p_multi, g_multi);
    cudaGetSymbolAddress((void**)&p_wh2,   g_wh2);
    cudaGetSymbolAddress((void**)&p_x,     g_x);
    cudaGetSymbolAddress((void**)&p_atoms_vec, g_atoms_vec);
    cudaGetSymbolAddress((void**)&p_av_att, g_av_att);
    cudaGetSymbolAddress((void**)&p_src1,  g_src1);
    cudaGetSymbolAddress((void**)&p_dst1,  g_dst1);
    cudaGetSymbolAddress((void**)&p_src2,  g_src2);
    cudaGetSymbolAddress((void**)&p_dst2,  g_dst2);
    cudaGetSymbolAddress((void**)&p_cnvA,  g_cnvA);
    cudaGetSymbolAddress((void**)&p_cnvB,  g_cnvB);
    cudaGetSymbolAddress((void**)&p_comp,  g_comp);
    cudaGetSymbolAddress((void**)&p_prot,  g_prot);
    cudaGetSymbolAddress((void**)&p_adjm,  g_adjmask);

    // fused prep
    k_prep<<<20901, 256>>>(adj, W_gat, W_go, conv_w, E_amino, atoms, E_atom);

    // ---- compound branch ----
    k_mm<0><<<dim3(128, 4), 256>>>(p_av, p_WcatT, nullptr, p_wh1, 8192, 256, 128);
    k_srcdst1<<<BB*NN_, 256>>>(a_gat);
    k_attn<1><<<dim3(8, 4, BB), 256>>>(p_wh1, p_src1, p_dst1, p_adjm, p_multi, 256);
    k_mm<0><<<dim3(128, 2), 256>>>(p_multi, p_WgoT, nullptr, p_wh2, 8192, 128, 256);
    k_srcdst2<<<BB*NN_, 128>>>(a_go);
    k_attn<0><<<dim3(8, 2, BB), 256>>>(p_wh2, p_src2, p_dst2, p_adjm, p_x, 128);
    k_mm<1><<<dim3(128, 2), 256>>>(p_x, W_comp_w, W_comp_b, p_atoms_vec, 8192, 128, 128);
    k_mm<1><<<dim3(128, 2), 256>>>(p_atoms_vec, W_att_w, W_att_b, p_av_att, 8192, 128, 128);
    k_mean_part<<<dim3(8, BB), 128>>>(p_av_att, atoms_mask, NN_);
    k_mean_fin<<<BB, 128>>>(p_comp);

    // ---- protein branch ----
    k_conv1<<<dim3(LL, BB), 128>>>(amino, conv_b);
    k_conv<<<dim3(64, BB), 256>>>(p_cnvA, p_cnvB, conv_w + 121,   conv_b + 1);
    k_conv<<<dim3(64, BB), 256>>>(p_cnvB, p_cnvA, conv_w + 2*121, conv_b + 2);
    k_mm<1><<<dim3(256, 2), 256>>>(p_cnvA, W_att_w, W_att_b, p_cnvB, 16384, 128, 128);
    k_mean_part<<<dim3(8, BB), 128>>>(p_cnvB, amino_mask, LL);
    k_mean_fin<<<BB, 128>>>(p_prot);

    // ---- head ----
    k_final<<<BB, 256>>>(pred_w, pred_b, out);
}

// round 8
// speedup vs baseline: 1.1536x; 1.1536x over previous
#include <cuda_runtime.h>
#include <cuda_bf16.h>
#include <math.h>
#include <stdint.h>

// ---------------- constants ----------------
#define BB   16
#define NN_  512
#define LL   1024
#define CD   128
#define GD   64
#define NH   4
#define LAT  128

// ---------------- scratch ----------------
__device__ float g_av       [BB*NN_*CD];
__device__ float g_wh1      [BB*NN_*(GD*NH)];
__device__ float g_multi    [BB*NN_*(GD*NH)];
__device__ float g_wh2      [BB*NN_*CD];
__device__ float g_x        [BB*NN_*CD];
__device__ float g_atoms_vec[BB*NN_*LAT];
__device__ float g_av_att   [BB*NN_*LAT];
__device__ float g_src1[BB*NH*NN_], g_dst1[BB*NH*NN_];
__device__ float g_src2[BB*NN_],    g_dst2[BB*NN_];
__device__ float g_cnvA[BB*LL*CD];
__device__ float g_cnvB[BB*LL*CD];
__device__ float g_T[30*11*CD];
__device__ float g_WcatT[256*128];
__device__ float g_WgoT [128*256];
__device__ float g_comp[BB*LAT], g_prot[BB*LAT];
__device__ float g_pp[BB*8*128];
__device__ float g_pm[BB*8];
__device__ uint32_t g_adjmask[BB*NN_*16];

__device__ __forceinline__ float lrelu(float x){ return x > 0.f ? x : 0.2f*x; }
__device__ __forceinline__ float eluf (float x){ return x > 0.f ? x : (__expf(x) - 1.f); }

// ---------------- f32x2 packed helpers (conv only) ----------------
__device__ __forceinline__ uint64_t pk2(float x){
    uint32_t xi = __float_as_uint(x);
    uint64_t r; asm("mov.b64 %0, {%1, %1};" : "=l"(r) : "r"(xi)); return r;
}
__device__ __forceinline__ uint64_t pk2f(float x, float y){
    uint32_t xi = __float_as_uint(x), yi = __float_as_uint(y);
    uint64_t r; asm("mov.b64 %0, {%1, %2};" : "=l"(r) : "r"(xi), "r"(yi)); return r;
}
__device__ __forceinline__ void fma2(uint64_t& d, uint64_t a, uint64_t b){
    asm("fma.rn.f32x2 %0, %1, %2, %0;" : "+l"(d) : "l"(a), "l"(b));
}
__device__ __forceinline__ float2 up2(uint64_t v){
    uint32_t lo, hi; asm("mov.b64 {%0, %1}, %2;" : "=r"(lo), "=r"(hi) : "l"(v));
    return make_float2(__uint_as_float(lo), __uint_as_float(hi));
}

// ---------------- bf16 helpers ----------------
__device__ __forceinline__ uint32_t packbf2(float x, float y){
    __nv_bfloat162 h = __floats2bfloat162_rn(x, y);
    return *(uint32_t*)&h;
}
__device__ __forceinline__ void split2(float x, float y, uint32_t& hi, uint32_t& lo){
    __nv_bfloat162 h = __floats2bfloat162_rn(x, y);
    float hx = __bfloat162float(h.x), hy = __bfloat162float(h.y);
    __nv_bfloat162 l = __floats2bfloat162_rn(x - hx, y - hy);
    hi = *(uint32_t*)&h; lo = *(uint32_t*)&l;
}
__device__ __forceinline__ uint32_t hadd2u(uint32_t a, uint32_t b){
    __nv_bfloat162 r = __hadd2(*(__nv_bfloat162*)&a, *(__nv_bfloat162*)&b);
    return *(uint32_t*)&r;
}
__device__ __forceinline__ uint32_t hmul2u(uint32_t a, uint32_t b){
    __nv_bfloat162 r = __hmul2(*(__nv_bfloat162*)&a, *(__nv_bfloat162*)&b);
    return *(uint32_t*)&r;
}

// mma.sync m16n8k16 bf16
__device__ __forceinline__ void mma16816(float* d, const uint32_t* a, const uint32_t* b){
    asm volatile(
        "mma.sync.aligned.m16n8k16.row.col.f32.bf16.bf16.f32 "
        "{%0,%1,%2,%3},{%4,%5,%6,%7},{%8,%9},{%0,%1,%2,%3};"
        : "+f"(d[0]), "+f"(d[1]), "+f"(d[2]), "+f"(d[3])
        : "r"(a[0]), "r"(a[1]), "r"(a[2]), "r"(a[3]), "r"(b[0]), "r"(b[1]));
}

// ---------------- fused prep kernel ----------------
__global__ void __launch_bounds__(256) k_prep(
    const int* __restrict__ adj, const float* __restrict__ W_gat,
    const float* __restrict__ W_go, const float* __restrict__ conv_w,
    const float* __restrict__ E_amino, const int* __restrict__ atoms,
    const float* __restrict__ E_atom)
{
    const int bid = blockIdx.x, tid = threadIdx.x;
    if (bid < 16384) {
        int t = bid*256 + tid;
        uint32_t bal = __ballot_sync(0xffffffffu, adj[t] > 0);
        if ((t & 31) == 0) g_adjmask[t >> 5] = bal;
    } else if (bid < 16512) {
        int idx = (bid - 16384)*256 + tid;
        int n = idx >> 7, k = idx & 127;
        int h = n >> 6, f = n & 63;
        g_WcatT[n*128 + k] = W_gat[((h*128) + k)*64 + f];
    } else if (bid < 16640) {
        int idx = (bid - 16512)*256 + tid;
        int n = idx >> 8, k = idx & 255;
        g_WgoT[n*256 + k] = W_go[k*128 + n];
    } else if (bid < 16805) {
        int idx = (bid - 16640)*256 + tid;
        if (idx < 42240) {
            int f = idx & 127, rest = idx >> 7;
            int dl = rest % 11, a = rest / 11;
            float acc = 0.f;
            #pragma unroll
            for (int df = 0; df < 11; ++df) {
                int fi = f + df - 5;
                if (fi >= 0 && fi < 128) acc += conv_w[dl*11 + df] * E_amino[a*128 + fi];
            }
            g_T[(a*11 + dl)*128 + f] = acc;
        }
    } else {
        int idx = (bid - 16805)*256 + tid;
        int row = idx >> 7, f = idx & 127;
        g_av[(size_t)row*128 + f] = E_atom[atoms[row]*128 + f];
    }
}

// ---------------- bf16-split tensor GEMM (64x64 tiles) ----------------
template<int ACT>
__global__ void __launch_bounds__(256) k_mm(
    const float* __restrict__ A, const float* __restrict__ BT,
    const float* __restrict__ bias, float* __restrict__ C,
    int M, int N, int K)
{
    __shared__ uint32_t Ah[2304], Al[2304], Bh[2304], Bl[2304];

    const int m0 = blockIdx.x*64, n0 = blockIdx.y*64;
    const int tid = threadIdx.x, w = tid >> 5, lane = tid & 31;
    const int wm = w & 3, wn = w >> 2;
    const int r4 = lane >> 2, cl = lane & 3;

    float acc[4][4];
    #pragma unroll
    for (int j = 0; j < 4; ++j)
        #pragma unroll
        for (int q = 0; q < 4; ++q) acc[j][q] = 0.f;

    for (int k0 = 0; k0 < K; k0 += 64) {
        __syncthreads();
        #pragma unroll
        for (int s = tid; s < 1024; s += 256) {
            int r = s >> 4, q = s & 15;
            float4 v = *(const float4*)&A[(size_t)(m0+r)*K + k0 + q*4];
            uint32_t h0,l0,h1,l1;
            split2(v.x, v.y, h0, l0); split2(v.z, v.w, h1, l1);
            int off = r*36 + q*2;
            Ah[off] = h0; Ah[off+1] = h1;
            Al[off] = l0; Al[off+1] = l1;
            float4 bv = *(const float4*)&BT[(size_t)(n0+r)*K + k0 + q*4];
            split2(bv.x, bv.y, h0, l0); split2(bv.z, bv.w, h1, l1);
            Bh[off] = h0; Bh[off+1] = h1;
            Bl[off] = l0; Bl[off+1] = l1;
        }
        __syncthreads();
        #pragma unroll
        for (int kk = 0; kk < 4; ++kk) {
            const int kw = kk*8;
            uint32_t ah[4], al[4];
            {
                int base = (wm*16 + r4)*36 + kw + cl;
                ah[0]=Ah[base];     ah[1]=Ah[base+288];
                ah[2]=Ah[base+4];   ah[3]=Ah[base+292];
                al[0]=Al[base];     al[1]=Al[base+288];
                al[2]=Al[base+4];   al[3]=Al[base+292];
            }
            uint32_t bh[4][2], bl[4][2];
            #pragma unroll
            for (int fn = 0; fn < 4; ++fn) {
                int base = (wn*32 + fn*8 + r4)*36 + kw + cl;
                bh[fn][0]=Bh[base]; bh[fn][1]=Bh[base+4];
                bl[fn][0]=Bl[base]; bl[fn][1]=Bl[base+4];
            }
            #pragma unroll
            for (int fn = 0; fn < 4; ++fn) {
                mma16816(acc[fn], ah, bh[fn]);
                mma16816(acc[fn], ah, bl[fn]);
                mma16816(acc[fn], al, bh[fn]);
            }
        }
    }
    #pragma unroll
    for (int fn = 0; fn < 4; ++fn) {
        int row = m0 + wm*16 + r4;
        int col = n0 + wn*32 + fn*8 + 2*cl;
        float b0 = 0.f, b1 = 0.f;
        if (bias) { b0 = bias[col]; b1 = bias[col+1]; }
        float v0 = acc[fn][0] + b0, v1 = acc[fn][1] + b1;
        float v2 = acc[fn][2] + b0, v3 = acc[fn][3] + b1;
        if (ACT) { v0=lrelu(v0); v1=lrelu(v1); v2=lrelu(v2); v3=lrelu(v3); }
        *(float2*)&C[(size_t)row*N + col]     = make_float2(v0, v1);
        *(float2*)&C[(size_t)(row+8)*N + col] = make_float2(v2, v3);
    }
}

// ---------------- GAT attention: 128-row i-tile, 64-col f-tile, packed A-build ----------------
// A in single bf16 (2 MMAs: Ah*Bh + Ah*Bl). ps sums rounded values (consistent normalize).
template<int MH>
__global__ void __launch_bounds__(256) k_attn(
    const float* __restrict__ wh, const float* __restrict__ src,
    const float* __restrict__ dst, const uint32_t* __restrict__ adjmask,
    float* __restrict__ out, int WS)
{
    __shared__ uint32_t Dp[256];     // bf16x2 (d_{2j}, d_{2j+1})
    __shared__ uint32_t PQ[512];     // bf16x2 (e^{d_j}, e^{0.2 d_j})
    __shared__ uint32_t sD2[128];    // bf16x2 (s_i, s_i)
    __shared__ uint32_t sPQ[128];    // bf16x2 (e^{s_i}, e^{0.2 s_i})
    __shared__ float Sum[128], pst[256];
    __shared__ uint32_t msk[2048];
    __shared__ uint32_t Ath[2304];   // 128 rows * 18 words (32 bf16 j's + pad)
    __shared__ uint32_t Bh[1152], Bl[1152];  // 64 f * 18 words

    const int it = blockIdx.x, hy = blockIdx.y, b = blockIdx.z;
    const int i0 = it*128;
    const int tid = threadIdx.x, w = tid >> 5, lane = tid & 31;
    const int r4 = lane >> 2, cl = lane & 3;
    const int whoff = hy*64;
    const int sdoff = MH ? (b*NH + hy) : b;

    const float* dstb = dst + (size_t)sdoff*512;
    const float* srcb = src + (size_t)sdoff*512;
    {
        float d0 = dstb[2*tid], d1 = dstb[2*tid + 1];
        Dp[tid] = packbf2(d0, d1);
        PQ[2*tid]     = packbf2(__expf(d0), __expf(0.2f*d0));
        PQ[2*tid + 1] = packbf2(__expf(d1), __expf(0.2f*d1));
    }
    if (tid < 128) {
        float s = srcb[i0 + tid];
        sD2[tid] = packbf2(s, s);
        sPQ[tid] = packbf2(__expf(s), __expf(0.2f*s));
    }
    {
        const uint32_t* mb = adjmask + ((size_t)(b*512) + i0)*16;
        for (int s = tid; s < 2048; s += 256) msk[s] = mb[s];
    }

    const int wm = w & 3, wn = w >> 2;     // 4 m-tiles x 2 n-tiles
    float acc[2][4][4];
    #pragma unroll
    for (int i = 0; i < 2; ++i)
        #pragma unroll
        for (int j = 0; j < 4; ++j)
            #pragma unroll
            for (int q = 0; q < 4; ++q) acc[i][j][q] = 0.f;

    const int ai = tid >> 1, half = tid & 1;
    __syncthreads();
    const uint32_t si2 = sD2[ai], piq = sPQ[ai];
    float ps = 0.f;

    for (int c = 0; c < 16; ++c) {
        const int j0 = c*32;
        if (c) __syncthreads();
        // --- A tile build (128 x 32), bf16, packed pipeline ---
        {
            uint32_t mw = msk[ai*16 + c];
            #pragma unroll
            for (int jp = 0; jp < 8; ++jp) {
                int jl0 = half*16 + jp*2, jl1 = jl0 + 1;
                uint32_t s2 = hadd2u(si2, Dp[c*16 + half*8 + jp]);
                uint32_t pr0 = hmul2u(PQ[j0 + jl0], piq);
                uint32_t pr1 = hmul2u(PQ[j0 + jl1], piq);
                uint32_t u0 = (s2 & 0x8000u)     ? (pr0 >> 16)          : (pr0 & 0xffffu);
                uint32_t u1 = (s2 & 0x80000000u) ? (pr1 & 0xffff0000u)  : (pr1 << 16);
                if (!((mw >> jl0) & 1u)) u0 = 0;
                if (!((mw >> jl1) & 1u)) u1 = 0;
                Ath[ai*18 + half*8 + jp] = u0 | u1;
                ps += __uint_as_float(u0 << 16) + __uint_as_float(u1);
            }
        }
        // --- B tile build: WhT [64 f x 32 j] hi/lo, paired 32-bit STS ---
        {
            const int f = tid & 63, jg = tid >> 6;   // 4 j-groups of 8
            #pragma unroll
            for (int p = 0; p < 4; ++p) {
                int jl = jg*8 + p*2;
                float v0 = wh[(size_t)(b*512 + j0 + jl)*WS + whoff + f];
                float v1 = wh[(size_t)(b*512 + j0 + jl + 1)*WS + whoff + f];
                uint32_t hw, lw; split2(v0, v1, hw, lw);
                Bh[f*18 + jg*4 + p] = hw;
                Bl[f*18 + jg*4 + p] = lw;
            }
        }
        __syncthreads();
        // --- MMA: 2 k-steps of 16 ---
        #pragma unroll
        for (int kk = 0; kk < 2; ++kk) {
            const int kw = kk*8;
            uint32_t ah[2][4];
            #pragma unroll
            for (int fm = 0; fm < 2; ++fm) {
                int base = (wm*32 + fm*16 + r4)*18 + kw + cl;
                ah[fm][0]=Ath[base];     ah[fm][1]=Ath[base+144];
                ah[fm][2]=Ath[base+4];   ah[fm][3]=Ath[base+148];
            }
            uint32_t bh[4][2], bl[4][2];
            #pragma unroll
            for (int fn = 0; fn < 4; ++fn) {
                int base = (wn*32 + fn*8 + r4)*18 + kw + cl;
                bh[fn][0]=Bh[base]; bh[fn][1]=Bh[base+4];
                bl[fn][0]=Bl[base]; bl[fn][1]=Bl[base+4];
            }
            #pragma unroll
            for (int fm = 0; fm < 2; ++fm)
                #pragma unroll
                for (int fn = 0; fn < 4; ++fn) {
                    mma16816(acc[fm][fn], ah[fm], bh[fn]);
                    mma16816(acc[fm][fn], ah[fm], bl[fn]);
                }
        }
    }
    pst[tid] = ps;
    __syncthreads();
    if (tid < 128) Sum[tid] = pst[2*tid] + pst[2*tid+1];
    __syncthreads();
    // --- epilogue: normalize + elu ---
    #pragma unroll
    for (int fm = 0; fm < 2; ++fm) {
        int rl = wm*32 + fm*16 + r4;
        float S0 = Sum[rl],   i0v = (S0 > 0.f) ? 1.f/S0 : 0.f;
        float S1 = Sum[rl+8], i1v = (S1 > 0.f) ? 1.f/S1 : 0.f;
        #pragma unroll
        for (int fn = 0; fn < 4; ++fn) {
            int col = whoff + wn*32 + fn*8 + 2*cl;
            float v0 = eluf(acc[fm][fn][0] * i0v);
            float v1 = eluf(acc[fm][fn][1] * i0v);
            float v2 = eluf(acc[fm][fn][2] * i1v);
            float v3 = eluf(acc[fm][fn][3] * i1v);
            *(float2*)&out[(size_t)(b*512 + i0 + rl)*WS + col]     = make_float2(v0, v1);
            *(float2*)&out[(size_t)(b*512 + i0 + rl + 8)*WS + col] = make_float2(v2, v3);
        }
    }
}

// ---------------- src/dst score kernels ----------------
__global__ void k_srcdst1(const float* __restrict__ a_gat){
    const int row = blockIdx.x;
    const int b = row >> 9, n = row & 511;
    const int tid = threadIdx.x;
    __shared__ float wrow[256];
    wrow[tid] = g_wh1[(size_t)row*256 + tid];
    __syncthreads();
    const int w = tid >> 5, l = tid & 31;
    const int h = w >> 1, half = w & 1;
    float v = wrow[h*64 + l]      * a_gat[h*128 + half*64 + l]
            + wrow[h*64 + 32 + l] * a_gat[h*128 + half*64 + 32 + l];
    #pragma unroll
    for (int o = 16; o; o >>= 1) v += __shfl_down_sync(0xffffffffu, v, o);
    if (l == 0) {
        float* outp = half ? g_dst1 : g_src1;
        outp[(size_t)(b*4 + h)*512 + n] = v;
    }
}
__global__ void k_srcdst2(const float* __restrict__ a_go){
    const int row = blockIdx.x;
    const int tid = threadIdx.x;
    __shared__ float wrow[128];
    __shared__ float part[4];
    wrow[tid] = g_wh2[(size_t)row*128 + tid];
    __syncthreads();
    const int w = tid >> 5, l = tid & 31;
    const int which = w >> 1, p = w & 1;
    float v = wrow[p*64 + l]      * a_go[which*128 + p*64 + l]
            + wrow[p*64 + 32 + l] * a_go[which*128 + p*64 + 32 + l];
    #pragma unroll
    for (int o = 16; o; o >>= 1) v += __shfl_down_sync(0xffffffffu, v, o);
    if (l == 0) part[w] = v;
    __syncthreads();
    if (tid == 0) g_src2[row] = part[0] + part[1];
    if (tid == 1) g_dst2[row] = part[2] + part[3];
}

// ---------------- CNN ----------------
__global__ void k_conv1(const int* __restrict__ amino, const float* __restrict__ conv_b){
    const int l = blockIdx.x, b = blockIdx.y, f = threadIdx.x;
    float acc = conv_b[0];
    #pragma unroll
    for (int dl = 0; dl < 11; ++dl) {
        int l2 = l + dl - 5;
        if (l2 >= 0 && l2 < 1024) {
            int id = amino[b*1024 + l2];
            acc += g_T[((size_t)id*11 + dl)*128 + f];
        }
    }
    g_cnvA[((size_t)(b*1024) + l)*128 + f] = fmaxf(acc, 0.f);
}
__global__ void __launch_bounds__(256) k_conv(
    const float* __restrict__ in, float* __restrict__ out,
    const float* __restrict__ wsrc, const float* __restrict__ bsrc)
{
    __shared__ float tile[26*139];
    __shared__ float ws[121];
    const int lb = blockIdx.x * 16, b = blockIdx.y;
    const int tid = threadIdx.x;
    if (tid < 121) ws[tid] = wsrc[tid];
    for (int idx = tid; idx < 26*138; idx += 256) {
        const int r = idx / 138, c = idx % 138;
        const int gl = lb + r - 5, gf = c - 5;
        float v = 0.f;
        if (gl >= 0 && gl < 1024 && gf >= 0 && gf < 128)
            v = in[((size_t)(b*1024) + gl)*128 + gf];
        tile[r*139 + c] = v;
    }
    __syncthreads();
    const int fg = tid >> 3, lg = tid & 7;
    const int f0 = fg * 4;
    uint64_t accp[4];
    {
        uint64_t bp = pk2(bsrc[0]);
        accp[0]=bp; accp[1]=bp; accp[2]=bp; accp[3]=bp;
    }
    for (int dl = 0; dl < 11; ++dl) {
        const float* w  = ws + dl*11;
        const float* r0 = tile + (lg + dl)*139 + f0;
        const float* r1 = r0 + 8*139;
        uint64_t vp[14];
        #pragma unroll
        for (int j = 0; j < 14; ++j) vp[j] = pk2f(r0[j], r1[j]);
        #pragma unroll
        for (int df = 0; df < 11; ++df) {
            uint64_t wv = pk2(w[df]);
            fma2(accp[0], wv, vp[df+0]);
            fma2(accp[1], wv, vp[df+1]);
            fma2(accp[2], wv, vp[df+2]);
            fma2(accp[3], wv, vp[df+3]);
        }
    }
    float* o0 = out + ((size_t)(b*1024) + lb + lg)*128 + f0;
    float* o1 = o0 + 8*128;
    #pragma unroll
    for (int k = 0; k < 4; ++k) {
        float2 v = up2(accp[k]);
        o0[k] = fmaxf(v.x, 0.f);
        o1[k] = fmaxf(v.y, 0.f);
    }
}

// ---------------- masked mean pooling ----------------
__global__ void k_mean_part(const float* __restrict__ in, const float* __restrict__ mask,
                            int NNd){
    const int ch = blockIdx.x, b = blockIdx.y, f = threadIdx.x;
    const int rows = NNd / 8;
    const int r0 = ch * rows;
    float s = 0.f, m = 0.f;
    #pragma unroll 4
    for (int n = r0; n < r0 + rows; ++n) {
        float mk = mask[b*NNd + n];
        m += mk;
        s += mk * in[((size_t)b*NNd + n)*128 + f];
    }
    g_pp[(size_t)(b*8 + ch)*128 + f] = s;
    if (f == 0) g_pm[b*8 + ch] = m;
}
__global__ void k_mean_fin(float* __restrict__ outp){
    const int b = blockIdx.x, f = threadIdx.x;
    float s = 0.f, m = 0.f;
    #pragma unroll
    for (int ch = 0; ch < 8; ++ch) {
        s += g_pp[(size_t)(b*8 + ch)*128 + f];
        m += g_pm[b*8 + ch];
    }
    outp[b*128 + f] = s / m;
}

// ---------------- final predictor ----------------
__global__ void k_final(const float* __restrict__ pred_w, const float* __restrict__ pred_b,
                        float* __restrict__ out){
    __shared__ float red[256];
    const int b = blockIdx.x, c = threadIdx.x;
    float v = (c < 128) ? g_comp[b*128 + c] : g_prot[b*128 + (c - 128)];
    v = v > 0.f ? v : 0.04f*v;
    red[c] = v * pred_w[c];
    __syncthreads();
    for (int s = 128; s > 0; s >>= 1) {
        if (c < s) red[c] += red[c + s];
        __syncthreads();
    }
    if (c == 0) out[b] = red[0] + pred_b[0];
}

// ---------------- launch ----------------
extern "C" void kernel_launch(void* const* d_in, const int* in_sizes, int n_in,
                              void* d_out, int out_size)
{
    const int*   atoms      = (const int*)  d_in[0];
    const float* atoms_mask = (const float*)d_in[1];
    const int*   adj        = (const int*)  d_in[2];
    const int*   amino      = (const int*)  d_in[3];
    const float* amino_mask = (const float*)d_in[4];
    const float* E_atom     = (const float*)d_in[5];
    const float* E_amino    = (const float*)d_in[6];
    const float* W_gat      = (const float*)d_in[7];
    const float* a_gat      = (const float*)d_in[8];
    const float* W_go       = (const float*)d_in[9];
    const float* a_go       = (const float*)d_in[10];
    const float* W_comp_w   = (const float*)d_in[11];
    const float* W_comp_b   = (const float*)d_in[12];
    const float* conv_w     = (const float*)d_in[13];
    const float* conv_b     = (const float*)d_in[14];
    const float* W_att_w    = (const float*)d_in[15];
    const float* W_att_b    = (const float*)d_in[16];
    const float* pred_w     = (const float*)d_in[17];
    const float* pred_b     = (const float*)d_in[18];
    float* out = (float*)d_out;

    float *p_WcatT, *p_WgoT;
    float *p_av, *p_wh1, *p_multi, *p_wh2, *p_x, *p_atoms_vec, *p_av_att;
    float *p_src1, *p_dst1, *p_src2, *p_dst2, *p_cnvA, *p_cnvB, *p_comp, *p_prot;
    uint32_t* p_adjm;
    cudaGetSymbolAddress((void**)&p_WcatT, g_WcatT);
    cudaGetSymbolAddress((void**)&p_WgoT,  g_WgoT);
    cudaGetSymbolAddress((void**)&p_av,    g_av);
    cudaGetSymbolAddress((void**)&p_wh1,   g_wh1);
    cudaGetSymbolAddress((void**)&p_multi, g_multi);
    cudaGetSymbolAddress((void**)&p_wh2,   g_wh2);
    cudaGetSymbolAddress((void**)&p_x,     g_x);
    cudaGetSymbolAddress((void**)&p_atoms_vec, g_atoms_vec);
    cudaGetSymbolAddress((void**)&p_av_att, g_av_att);
    cudaGetSymbolAddress((void**)&p_src1,  g_src1);
    cudaGetSymbolAddress((void**)&p_dst1,  g_dst1);
    cudaGetSymbolAddress((void**)&p_src2,  g_src2);
    cudaGetSymbolAddress((void**)&p_dst2,  g_dst2);
    cudaGetSymbolAddress((void**)&p_cnvA,  g_cnvA);
    cudaGetSymbolAddress((void**)&p_cnvB,  g_cnvB);
    cudaGetSymbolAddress((void**)&p_comp,  g_comp);
    cudaGetSymbolAddress((void**)&p_prot,  g_prot);
    cudaGetSymbolAddress((void**)&p_adjm,  g_adjmask);

    // fused prep
    k_prep<<<20901, 256>>>(adj, W_gat, W_go, conv_w, E_amino, atoms, E_atom);

    // ---- compound branch ----
    k_mm<0><<<dim3(128, 4), 256>>>(p_av, p_WcatT, nullptr, p_wh1, 8192, 256, 128);
    k_srcdst1<<<BB*NN_, 256>>>(a_gat);
    k_attn<1><<<dim3(4, 4, BB), 256>>>(p_wh1, p_src1, p_dst1, p_adjm, p_multi, 256);
    k_mm<0><<<dim3(128, 2), 256>>>(p_multi, p_WgoT, nullptr, p_wh2, 8192, 128, 256);
    k_srcdst2<<<BB*NN_, 128>>>(a_go);
    k_attn<0><<<dim3(4, 2, BB), 256>>>(p_wh2, p_src2, p_dst2, p_adjm, p_x, 128);
    k_mm<1><<<dim3(128, 2), 256>>>(p_x, W_comp_w, W_comp_b, p_atoms_vec, 8192, 128, 128);
    k_mm<1><<<dim3(128, 2), 256>>>(p_atoms_vec, W_att_w, W_att_b, p_av_att, 8192, 128, 128);
    k_mean_part<<<dim3(8, BB), 128>>>(p_av_att, atoms_mask, NN_);
    k_mean_fin<<<BB, 128>>>(p_comp);

    // ---- protein branch ----
    k_conv1<<<dim3(LL, BB), 128>>>(amino, conv_b);
    k_conv<<<dim3(64, BB), 256>>>(p_cnvA, p_cnvB, conv_w + 121,   conv_b + 1);
    k_conv<<<dim3(64, BB), 256>>>(p_cnvB, p_cnvA, conv_w + 2*121, conv_b + 2);
    k_mm<1><<<dim3(256, 2), 256>>>(p_cnvA, W_att_w, W_att_b, p_cnvB, 16384, 128, 128);
    k_mean_part<<<dim3(8, BB), 128>>>(p_cnvB, amino_mask, LL);
    k_mean_fin<<<BB, 128>>>(p_prot);

    // ---- head ----
    k_final<<<BB, 256>>>(pred_w, pred_b, out);
}

// round 9
// speedup vs baseline: 1.3638x; 1.1822x over previous
#include <cuda_runtime.h>
#include <cuda_bf16.h>
#include <cuda_fp16.h>
#include <math.h>
#include <stdint.h>

// ---------------- constants ----------------
#define BB   16
#define NN_  512
#define LL   1024
#define CD   128
#define GD   64
#define NH   4
#define LAT  128

// ---------------- scratch ----------------
__device__ float g_av       [BB*NN_*CD];
__device__ float g_wh1      [BB*NN_*(GD*NH)];
__device__ float g_multi    [BB*NN_*(GD*NH)];
__device__ float g_wh2      [BB*NN_*CD];
__device__ float g_x        [BB*NN_*CD];
__device__ float g_atoms_vec[BB*NN_*LAT];
__device__ float g_av_att   [BB*NN_*LAT];
__device__ float g_src1[BB*NH*NN_], g_dst1[BB*NH*NN_];
__device__ float g_src2[BB*NN_],    g_dst2[BB*NN_];
__device__ float g_cnvA[BB*LL*CD];
__device__ float g_cnvB[BB*LL*CD];
__device__ float g_T[30*11*CD];
__device__ float g_WcatT[256*128];
__device__ float g_WgoT [128*256];
__device__ float g_comp[BB*LAT], g_prot[BB*LAT];
__device__ float g_pp [BB*8*128];   // compound pooling scratch
__device__ float g_pm [BB*8];
__device__ float g_pp2[BB*8*128];   // protein pooling scratch (stream-parallel)
__device__ float g_pm2[BB*8];
__device__ uint32_t g_adjmask[BB*NN_*16];

__device__ __forceinline__ float lrelu(float x){ return x > 0.f ? x : 0.2f*x; }
__device__ __forceinline__ float eluf (float x){ return x > 0.f ? x : (__expf(x) - 1.f); }

// ---------------- f32x2 packed helpers (conv only) ----------------
__device__ __forceinline__ uint64_t pk2(float x){
    uint32_t xi = __float_as_uint(x);
    uint64_t r; asm("mov.b64 %0, {%1, %1};" : "=l"(r) : "r"(xi)); return r;
}
__device__ __forceinline__ uint64_t pk2f(float x, float y){
    uint32_t xi = __float_as_uint(x), yi = __float_as_uint(y);
    uint64_t r; asm("mov.b64 %0, {%1, %2};" : "=l"(r) : "r"(xi), "r"(yi)); return r;
}
__device__ __forceinline__ void fma2(uint64_t& d, uint64_t a, uint64_t b){
    asm("fma.rn.f32x2 %0, %1, %2, %0;" : "+l"(d) : "l"(a), "l"(b));
}
__device__ __forceinline__ float2 up2(uint64_t v){
    uint32_t lo, hi; asm("mov.b64 {%0, %1}, %2;" : "=r"(lo), "=r"(hi) : "l"(v));
    return make_float2(__uint_as_float(lo), __uint_as_float(hi));
}

// ---------------- bf16 helpers (k_mm) ----------------
__device__ __forceinline__ void split2(float x, float y, uint32_t& hi, uint32_t& lo){
    __nv_bfloat162 h = __floats2bfloat162_rn(x, y);
    float hx = __bfloat162float(h.x), hy = __bfloat162float(h.y);
    __nv_bfloat162 l = __floats2bfloat162_rn(x - hx, y - hy);
    hi = *(uint32_t*)&h; lo = *(uint32_t*)&l;
}
// bf16 mma
__device__ __forceinline__ void mma16816(float* d, const uint32_t* a, const uint32_t* b){
    asm volatile(
        "mma.sync.aligned.m16n8k16.row.col.f32.bf16.bf16.f32 "
        "{%0,%1,%2,%3},{%4,%5,%6,%7},{%8,%9},{%0,%1,%2,%3};"
        : "+f"(d[0]), "+f"(d[1]), "+f"(d[2]), "+f"(d[3])
        : "r"(a[0]), "r"(a[1]), "r"(a[2]), "r"(a[3]), "r"(b[0]), "r"(b[1]));
}

// ---------------- fp16 helpers (attention) ----------------
__device__ __forceinline__ uint32_t packhf2(float x, float y){
    __half2 h = __floats2half2_rn(x, y);
    return *(uint32_t*)&h;
}
__device__ __forceinline__ uint32_t hadd2uh(uint32_t a, uint32_t b){
    __half2 r = __hadd2(*(__half2*)&a, *(__half2*)&b);
    return *(uint32_t*)&r;
}
__device__ __forceinline__ uint32_t hmul2uh(uint32_t a, uint32_t b){
    __half2 r = __hmul2(*(__half2*)&a, *(__half2*)&b);
    return *(uint32_t*)&r;
}
__device__ __forceinline__ float2 h2f2(uint32_t w){
    return __half22float2(*(__half2*)&w);
}
// fp16 mma
__device__ __forceinline__ void mma16816h(float* d, const uint32_t* a, const uint32_t* b){
    asm volatile(
        "mma.sync.aligned.m16n8k16.row.col.f32.f16.f16.f32 "
        "{%0,%1,%2,%3},{%4,%5,%6,%7},{%8,%9},{%0,%1,%2,%3};"
        : "+f"(d[0]), "+f"(d[1]), "+f"(d[2]), "+f"(d[3])
        : "r"(a[0]), "r"(a[1]), "r"(a[2]), "r"(a[3]), "r"(b[0]), "r"(b[1]));
}

// ---------------- fused prep kernel ----------------
__global__ void __launch_bounds__(256) k_prep(
    const int* __restrict__ adj, const float* __restrict__ W_gat,
    const float* __restrict__ W_go, const float* __restrict__ conv_w,
    const float* __restrict__ E_amino, const int* __restrict__ atoms,
    const float* __restrict__ E_atom)
{
    const int bid = blockIdx.x, tid = threadIdx.x;
    if (bid < 16384) {
        int t = bid*256 + tid;
        uint32_t bal = __ballot_sync(0xffffffffu, adj[t] > 0);
        if ((t & 31) == 0) g_adjmask[t >> 5] = bal;
    } else if (bid < 16512) {
        int idx = (bid - 16384)*256 + tid;
        int n = idx >> 7, k = idx & 127;
        int h = n >> 6, f = n & 63;
        g_WcatT[n*128 + k] = W_gat[((h*128) + k)*64 + f];
    } else if (bid < 16640) {
        int idx = (bid - 16512)*256 + tid;
        int n = idx >> 8, k = idx & 255;
        g_WgoT[n*256 + k] = W_go[k*128 + n];
    } else if (bid < 16805) {
        int idx = (bid - 16640)*256 + tid;
        if (idx < 42240) {
            int f = idx & 127, rest = idx >> 7;
            int dl = rest % 11, a = rest / 11;
            float acc = 0.f;
            #pragma unroll
            for (int df = 0; df < 11; ++df) {
                int fi = f + df - 5;
                if (fi >= 0 && fi < 128) acc += conv_w[dl*11 + df] * E_amino[a*128 + fi];
            }
            g_T[(a*11 + dl)*128 + f] = acc;
        }
    } else {
        int idx = (bid - 16805)*256 + tid;
        int row = idx >> 7, f = idx & 127;
        g_av[(size_t)row*128 + f] = E_atom[atoms[row]*128 + f];
    }
}

// ---------------- bf16-split tensor GEMM (64x64 tiles) ----------------
template<int ACT>
__global__ void __launch_bounds__(256) k_mm(
    const float* __restrict__ A, const float* __restrict__ BT,
    const float* __restrict__ bias, float* __restrict__ C,
    int M, int N, int K)
{
    __shared__ uint32_t Ah[2304], Al[2304], Bh[2304], Bl[2304];

    const int m0 = blockIdx.x*64, n0 = blockIdx.y*64;
    const int tid = threadIdx.x, w = tid >> 5, lane = tid & 31;
    const int wm = w & 3, wn = w >> 2;
    const int r4 = lane >> 2, cl = lane & 3;

    float acc[4][4];
    #pragma unroll
    for (int j = 0; j < 4; ++j)
        #pragma unroll
        for (int q = 0; q < 4; ++q) acc[j][q] = 0.f;

    for (int k0 = 0; k0 < K; k0 += 64) {
        __syncthreads();
        #pragma unroll
        for (int s = tid; s < 1024; s += 256) {
            int r = s >> 4, q = s & 15;
            float4 v = *(const float4*)&A[(size_t)(m0+r)*K + k0 + q*4];
            uint32_t h0,l0,h1,l1;
            split2(v.x, v.y, h0, l0); split2(v.z, v.w, h1, l1);
            int off = r*36 + q*2;
            Ah[off] = h0; Ah[off+1] = h1;
            Al[off] = l0; Al[off+1] = l1;
            float4 bv = *(const float4*)&BT[(size_t)(n0+r)*K + k0 + q*4];
            split2(bv.x, bv.y, h0, l0); split2(bv.z, bv.w, h1, l1);
            Bh[off] = h0; Bh[off+1] = h1;
            Bl[off] = l0; Bl[off+1] = l1;
        }
        __syncthreads();
        #pragma unroll
        for (int kk = 0; kk < 4; ++kk) {
            const int kw = kk*8;
            uint32_t ah[4], al[4];
            {
                int base = (wm*16 + r4)*36 + kw + cl;
                ah[0]=Ah[base];     ah[1]=Ah[base+288];
                ah[2]=Ah[base+4];   ah[3]=Ah[base+292];
                al[0]=Al[base];     al[1]=Al[base+288];
                al[2]=Al[base+4];   al[3]=Al[base+292];
            }
            uint32_t bh[4][2], bl[4][2];
            #pragma unroll
            for (int fn = 0; fn < 4; ++fn) {
                int base = (wn*32 + fn*8 + r4)*36 + kw + cl;
                bh[fn][0]=Bh[base]; bh[fn][1]=Bh[base+4];
                bl[fn][0]=Bl[base]; bl[fn][1]=Bl[base+4];
            }
            #pragma unroll
            for (int fn = 0; fn < 4; ++fn) {
                mma16816(acc[fn], ah, bh[fn]);
                mma16816(acc[fn], ah, bl[fn]);
                mma16816(acc[fn], al, bh[fn]);
            }
        }
    }
    #pragma unroll
    for (int fn = 0; fn < 4; ++fn) {
        int row = m0 + wm*16 + r4;
        int col = n0 + wn*32 + fn*8 + 2*cl;
        float b0 = 0.f, b1 = 0.f;
        if (bias) { b0 = bias[col]; b1 = bias[col+1]; }
        float v0 = acc[fn][0] + b0, v1 = acc[fn][1] + b1;
        float v2 = acc[fn][2] + b0, v3 = acc[fn][3] + b1;
        if (ACT) { v0=lrelu(v0); v1=lrelu(v1); v2=lrelu(v2); v3=lrelu(v3); }
        *(float2*)&C[(size_t)row*N + col]     = make_float2(v0, v1);
        *(float2*)&C[(size_t)(row+8)*N + col] = make_float2(v2, v3);
    }
}

// ---------------- GAT attention: fp16, 128-row i-tile, 64-col f-tile ----------------
// A single fp16 (packed build), B hi/lo fp16 -> 2 MMAs. ps sums rounded fp16 values.
template<int MH>
__global__ void __launch_bounds__(256) k_attn(
    const float* __restrict__ wh, const float* __restrict__ src,
    const float* __restrict__ dst, const uint32_t* __restrict__ adjmask,
    float* __restrict__ out, int WS)
{
    __shared__ uint32_t Dp[256];     // fp16x2 (d_{2j}, d_{2j+1})
    __shared__ uint32_t PQ[512];     // fp16x2 (e^{d_j}, e^{0.2 d_j})
    __shared__ uint32_t sD2[128];    // fp16x2 (s_i, s_i)
    __shared__ uint32_t sPQ[128];    // fp16x2 (e^{s_i}, e^{0.2 s_i})
    __shared__ float Sum[128], pst[256];
    __shared__ uint32_t msk[2048];
    __shared__ uint32_t Ath[2304];   // 128 rows * 18 words
    __shared__ uint32_t Bh[1152], Bl[1152];  // 64 f * 18 words

    const int it = blockIdx.x, hy = blockIdx.y, b = blockIdx.z;
    const int i0 = it*128;
    const int tid = threadIdx.x, w = tid >> 5, lane = tid & 31;
    const int r4 = lane >> 2, cl = lane & 3;
    const int whoff = hy*64;
    const int sdoff = MH ? (b*NH + hy) : b;

    const float* dstb = dst + (size_t)sdoff*512;
    const float* srcb = src + (size_t)sdoff*512;
    {
        float d0 = dstb[2*tid], d1 = dstb[2*tid + 1];
        Dp[tid] = packhf2(d0, d1);
        PQ[2*tid]     = packhf2(__expf(d0), __expf(0.2f*d0));
        PQ[2*tid + 1] = packhf2(__expf(d1), __expf(0.2f*d1));
    }
    if (tid < 128) {
        float s = srcb[i0 + tid];
        sD2[tid] = packhf2(s, s);
        sPQ[tid] = packhf2(__expf(s), __expf(0.2f*s));
    }
    {
        const uint32_t* mb = adjmask + ((size_t)(b*512) + i0)*16;
        for (int s = tid; s < 2048; s += 256) msk[s] = mb[s];
    }

    const int wm = w & 3, wn = w >> 2;
    float acc[2][4][4];
    #pragma unroll
    for (int i = 0; i < 2; ++i)
        #pragma unroll
        for (int j = 0; j < 4; ++j)
            #pragma unroll
            for (int q = 0; q < 4; ++q) acc[i][j][q] = 0.f;

    const int ai = tid >> 1, half = tid & 1;
    __syncthreads();
    const uint32_t si2 = sD2[ai], piq = sPQ[ai];
    float ps = 0.f;

    for (int c = 0; c < 16; ++c) {
        const int j0 = c*32;
        if (c) __syncthreads();
        // --- A tile build (128 x 32), fp16 packed pipeline ---
        {
            uint32_t mw = msk[ai*16 + c];
            #pragma unroll
            for (int jp = 0; jp < 8; ++jp) {
                int jl0 = half*16 + jp*2, jl1 = jl0 + 1;
                uint32_t s2 = hadd2uh(si2, Dp[c*16 + half*8 + jp]);
                uint32_t pr0 = hmul2uh(PQ[j0 + jl0], piq);
                uint32_t pr1 = hmul2uh(PQ[j0 + jl1], piq);
                uint32_t u0 = (s2 & 0x8000u)     ? (pr0 >> 16)          : (pr0 & 0xffffu);
                uint32_t u1 = (s2 & 0x80000000u) ? (pr1 & 0xffff0000u)  : (pr1 << 16);
                if (!((mw >> jl0) & 1u)) u0 = 0;
                if (!((mw >> jl1) & 1u)) u1 = 0;
                uint32_t word = u0 | u1;
                Ath[ai*18 + half*8 + jp] = word;
                float2 f = h2f2(word);
                ps += f.x + f.y;
            }
        }
        // --- B tile build: WhT [64 f x 32 j] fp16 hi/lo, paired 32-bit STS ---
        {
            const int f = tid & 63, jg = tid >> 6;
            #pragma unroll
            for (int p = 0; p < 4; ++p) {
                int jl = jg*8 + p*2;
                float v0 = wh[(size_t)(b*512 + j0 + jl)*WS + whoff + f];
                float v1 = wh[(size_t)(b*512 + j0 + jl + 1)*WS + whoff + f];
                uint32_t hw = packhf2(v0, v1);
                float2 hv = h2f2(hw);
                uint32_t lw = packhf2(v0 - hv.x, v1 - hv.y);
                Bh[f*18 + jg*4 + p] = hw;
                Bl[f*18 + jg*4 + p] = lw;
            }
        }
        __syncthreads();
        // --- MMA: 2 k-steps of 16 ---
        #pragma unroll
        for (int kk = 0; kk < 2; ++kk) {
            const int kw = kk*8;
            uint32_t ah[2][4];
            #pragma unroll
            for (int fm = 0; fm < 2; ++fm) {
                int base = (wm*32 + fm*16 + r4)*18 + kw + cl;
                ah[fm][0]=Ath[base];     ah[fm][1]=Ath[base+144];
                ah[fm][2]=Ath[base+4];   ah[fm][3]=Ath[base+148];
            }
            uint32_t bh[4][2], bl[4][2];
            #pragma unroll
            for (int fn = 0; fn < 4; ++fn) {
                int base = (wn*32 + fn*8 + r4)*18 + kw + cl;
                bh[fn][0]=Bh[base]; bh[fn][1]=Bh[base+4];
                bl[fn][0]=Bl[base]; bl[fn][1]=Bl[base+4];
            }
            #pragma unroll
            for (int fm = 0; fm < 2; ++fm)
                #pragma unroll
                for (int fn = 0; fn < 4; ++fn) {
                    mma16816h(acc[fm][fn], ah[fm], bh[fn]);
                    mma16816h(acc[fm][fn], ah[fm], bl[fn]);
                }
        }
    }
    pst[tid] = ps;
    __syncthreads();
    if (tid < 128) Sum[tid] = pst[2*tid] + pst[2*tid+1];
    __syncthreads();
    // --- epilogue: normalize + elu ---
    #pragma unroll
    for (int fm = 0; fm < 2; ++fm) {
        int rl = wm*32 + fm*16 + r4;
        float S0 = Sum[rl],   i0v = (S0 > 0.f) ? 1.f/S0 : 0.f;
        float S1 = Sum[rl+8], i1v = (S1 > 0.f) ? 1.f/S1 : 0.f;
        #pragma unroll
        for (int fn = 0; fn < 4; ++fn) {
            int col = whoff + wn*32 + fn*8 + 2*cl;
            float v0 = eluf(acc[fm][fn][0] * i0v);
            float v1 = eluf(acc[fm][fn][1] * i0v);
            float v2 = eluf(acc[fm][fn][2] * i1v);
            float v3 = eluf(acc[fm][fn][3] * i1v);
            *(float2*)&out[(size_t)(b*512 + i0 + rl)*WS + col]     = make_float2(v0, v1);
            *(float2*)&out[(size_t)(b*512 + i0 + rl + 8)*WS + col] = make_float2(v2, v3);
        }
    }
}

// ---------------- src/dst score kernels ----------------
__global__ void k_srcdst1(const float* __restrict__ a_gat){
    const int row = blockIdx.x;
    const int b = row >> 9, n = row & 511;
    const int tid = threadIdx.x;
    __shared__ float wrow[256];
    wrow[tid] = g_wh1[(size_t)row*256 + tid];
    __syncthreads();
    const int w = tid >> 5, l = tid & 31;
    const int h = w >> 1, half = w & 1;
    float v = wrow[h*64 + l]      * a_gat[h*128 + half*64 + l]
            + wrow[h*64 + 32 + l] * a_gat[h*128 + half*64 + 32 + l];
    #pragma unroll
    for (int o = 16; o; o >>= 1) v += __shfl_down_sync(0xffffffffu, v, o);
    if (l == 0) {
        float* outp = half ? g_dst1 : g_src1;
        outp[(size_t)(b*4 + h)*512 + n] = v;
    }
}
__global__ void k_srcdst2(const float* __restrict__ a_go){
    const int row = blockIdx.x;
    const int tid = threadIdx.x;
    __shared__ float wrow[128];
    __shared__ float part[4];
    wrow[tid] = g_wh2[(size_t)row*128 + tid];
    __syncthreads();
    const int w = tid >> 5, l = tid & 31;
    const int which = w >> 1, p = w & 1;
    float v = wrow[p*64 + l]      * a_go[which*128 + p*64 + l]
            + wrow[p*64 + 32 + l] * a_go[which*128 + p*64 + 32 + l];
    #pragma unroll
    for (int o = 16; o; o >>= 1) v += __shfl_down_sync(0xffffffffu, v, o);
    if (l == 0) part[w] = v;
    __syncthreads();
    if (tid == 0) g_src2[row] = part[0] + part[1];
    if (tid == 1) g_dst2[row] = part[2] + part[3];
}

// ---------------- CNN ----------------
__global__ void k_conv1(const int* __restrict__ amino, const float* __restrict__ conv_b){
    const int l = blockIdx.x, b = blockIdx.y, f = threadIdx.x;
    float acc = conv_b[0];
    #pragma unroll
    for (int dl = 0; dl < 11; ++dl) {
        int l2 = l + dl - 5;
        if (l2 >= 0 && l2 < 1024) {
            int id = amino[b*1024 + l2];
            acc += g_T[((size_t)id*11 + dl)*128 + f];
        }
    }
    g_cnvA[((size_t)(b*1024) + l)*128 + f] = fmaxf(acc, 0.f);
}
__global__ void __launch_bounds__(256) k_conv(
    const float* __restrict__ in, float* __restrict__ out,
    const float* __restrict__ wsrc, const float* __restrict__ bsrc)
{
    __shared__ float tile[26*139];
    __shared__ float ws[121];
    const int lb = blockIdx.x * 16, b = blockIdx.y;
    const int tid = threadIdx.x;
    if (tid < 121) ws[tid] = wsrc[tid];
    for (int idx = tid; idx < 26*138; idx += 256) {
        const int r = idx / 138, c = idx % 138;
        const int gl = lb + r - 5, gf = c - 5;
        float v = 0.f;
        if (gl >= 0 && gl < 1024 && gf >= 0 && gf < 128)
            v = in[((size_t)(b*1024) + gl)*128 + gf];
        tile[r*139 + c] = v;
    }
    __syncthreads();
    const int fg = tid >> 3, lg = tid & 7;
    const int f0 = fg * 4;
    uint64_t accp[4];
    {
        uint64_t bp = pk2(bsrc[0]);
        accp[0]=bp; accp[1]=bp; accp[2]=bp; accp[3]=bp;
    }
    for (int dl = 0; dl < 11; ++dl) {
        const float* w  = ws + dl*11;
        const float* r0 = tile + (lg + dl)*139 + f0;
        const float* r1 = r0 + 8*139;
        uint64_t vp[14];
        #pragma unroll
        for (int j = 0; j < 14; ++j) vp[j] = pk2f(r0[j], r1[j]);
        #pragma unroll
        for (int df = 0; df < 11; ++df) {
            uint64_t wv = pk2(w[df]);
            fma2(accp[0], wv, vp[df+0]);
            fma2(accp[1], wv, vp[df+1]);
            fma2(accp[2], wv, vp[df+2]);
            fma2(accp[3], wv, vp[df+3]);
        }
    }
    float* o0 = out + ((size_t)(b*1024) + lb + lg)*128 + f0;
    float* o1 = o0 + 8*128;
    #pragma unroll
    for (int k = 0; k < 4; ++k) {
        float2 v = up2(accp[k]);
        o0[k] = fmaxf(v.x, 0.f);
        o1[k] = fmaxf(v.y, 0.f);
    }
}

// ---------------- masked mean pooling (parameterized scratch) ----------------
__global__ void k_mean_part(const float* __restrict__ in, const float* __restrict__ mask,
                            float* __restrict__ pp, float* __restrict__ pm, int NNd){
    const int ch = blockIdx.x, b = blockIdx.y, f = threadIdx.x;
    const int rows = NNd / 8;
    const int r0 = ch * rows;
    float s = 0.f, m = 0.f;
    #pragma unroll 4
    for (int n = r0; n < r0 + rows; ++n) {
        float mk = mask[b*NNd + n];
        m += mk;
        s += mk * in[((size_t)b*NNd + n)*128 + f];
    }
    pp[(size_t)(b*8 + ch)*128 + f] = s;
    if (f == 0) pm[b*8 + ch] = m;
}
__global__ void k_mean_fin(const float* __restrict__ pp, const float* __restrict__ pm,
                           float* __restrict__ outp){
    const int b = blockIdx.x, f = threadIdx.x;
    float s = 0.f, m = 0.f;
    #pragma unroll
    for (int ch = 0; ch < 8; ++ch) {
        s += pp[(size_t)(b*8 + ch)*128 + f];
        m += pm[b*8 + ch];
    }
    outp[b*128 + f] = s / m;
}

// ---------------- final predictor ----------------
__global__ void k_final(const float* __restrict__ pred_w, const float* __restrict__ pred_b,
                        float* __restrict__ out){
    __shared__ float red[256];
    const int b = blockIdx.x, c = threadIdx.x;
    float v = (c < 128) ? g_comp[b*128 + c] : g_prot[b*128 + (c - 128)];
    v = v > 0.f ? v : 0.04f*v;
    red[c] = v * pred_w[c];
    __syncthreads();
    for (int s = 128; s > 0; s >>= 1) {
        if (c < s) red[c] += red[c + s];
        __syncthreads();
    }
    if (c == 0) out[b] = red[0] + pred_b[0];
}

// ---------------- launch ----------------
extern "C" void kernel_launch(void* const* d_in, const int* in_sizes, int n_in,
                              void* d_out, int out_size)
{
    const int*   atoms      = (const int*)  d_in[0];
    const float* atoms_mask = (const float*)d_in[1];
    const int*   adj        = (const int*)  d_in[2];
    const int*   amino      = (const int*)  d_in[3];
    const float* amino_mask = (const float*)d_in[4];
    const float* E_atom     = (const float*)d_in[5];
    const float* E_amino    = (const float*)d_in[6];
    const float* W_gat      = (const float*)d_in[7];
    const float* a_gat      = (const float*)d_in[8];
    const float* W_go       = (const float*)d_in[9];
    const float* a_go       = (const float*)d_in[10];
    const float* W_comp_w   = (const float*)d_in[11];
    const float* W_comp_b   = (const float*)d_in[12];
    const float* conv_w     = (const float*)d_in[13];
    const float* conv_b     = (const float*)d_in[14];
    const float* W_att_w    = (const float*)d_in[15];
    const float* W_att_b    = (const float*)d_in[16];
    const float* pred_w     = (const float*)d_in[17];
    const float* pred_b     = (const float*)d_in[18];
    float* out = (float*)d_out;

    float *p_WcatT, *p_WgoT;
    float *p_av, *p_wh1, *p_multi, *p_wh2, *p_x, *p_atoms_vec, *p_av_att;
    float *p_src1, *p_dst1, *p_src2, *p_dst2, *p_cnvA, *p_cnvB, *p_comp, *p_prot;
    float *p_pp, *p_pm, *p_pp2, *p_pm2;
    uint32_t* p_adjm;
    cudaGetSymbolAddress((void**)&p_WcatT, g_WcatT);
    cudaGetSymbolAddress((void**)&p_WgoT,  g_WgoT);
    cudaGetSymbolAddress((void**)&p_av,    g_av);
    cudaGetSymbolAddress((void**)&p_wh1,   g_wh1);
    cudaGetSymbolAddress((void**)&p_multi, g_multi);
    cudaGetSymbolAddress((void**)&p_wh2,   g_wh2);
    cudaGetSymbolAddress((void**)&p_x,     g_x);
    cudaGetSymbolAddress((void**)&p_atoms_vec, g_atoms_vec);
    cudaGetSymbolAddress((void**)&p_av_att, g_av_att);
    cudaGetSymbolAddress((void**)&p_src1,  g_src1);
    cudaGetSymbolAddress((void**)&p_dst1,  g_dst1);
    cudaGetSymbolAddress((void**)&p_src2,  g_src2);
    cudaGetSymbolAddress((void**)&p_dst2,  g_dst2);
    cudaGetSymbolAddress((void**)&p_cnvA,  g_cnvA);
    cudaGetSymbolAddress((void**)&p_cnvB,  g_cnvB);
    cudaGetSymbolAddress((void**)&p_comp,  g_comp);
    cudaGetSymbolAddress((void**)&p_prot,  g_prot);
    cudaGetSymbolAddress((void**)&p_pp,    g_pp);
    cudaGetSymbolAddress((void**)&p_pm,    g_pm);
    cudaGetSymbolAddress((void**)&p_pp2,   g_pp2);
    cudaGetSymbolAddress((void**)&p_pm2,   g_pm2);
    cudaGetSymbolAddress((void**)&p_adjm,  g_adjmask);

    // stream fork for the independent protein branch (captured via events)
    cudaStream_t s2;
    cudaStreamCreateWithFlags(&s2, cudaStreamNonBlocking);
    cudaEvent_t evF, evJ;
    cudaEventCreateWithFlags(&evF, cudaEventDisableTiming);
    cudaEventCreateWithFlags(&evJ, cudaEventDisableTiming);

    // fused prep (both branches depend on it)
    k_prep<<<20901, 256>>>(adj, W_gat, W_go, conv_w, E_amino, atoms, E_atom);
    cudaEventRecord(evF, 0);
    cudaStreamWaitEvent(s2, evF, 0);

    // ---- protein branch (stream s2) ----
    k_conv1<<<dim3(LL, BB), 128, 0, s2>>>(amino, conv_b);
    k_conv<<<dim3(64, BB), 256, 0, s2>>>(p_cnvA, p_cnvB, conv_w + 121,   conv_b + 1);
    k_conv<<<dim3(64, BB), 256, 0, s2>>>(p_cnvB, p_cnvA, conv_w + 2*121, conv_b + 2);
    k_mm<1><<<dim3(256, 2), 256, 0, s2>>>(p_cnvA, W_att_w, W_att_b, p_cnvB, 16384, 128, 128);
    k_mean_part<<<dim3(8, BB), 128, 0, s2>>>(p_cnvB, amino_mask, p_pp2, p_pm2, LL);
    k_mean_fin<<<BB, 128, 0, s2>>>(p_pp2, p_pm2, p_prot);
    cudaEventRecord(evJ, s2);

    // ---- compound branch (default stream, concurrent) ----
    k_mm<0><<<dim3(128, 4), 256>>>(p_av, p_WcatT, nullptr, p_wh1, 8192, 256, 128);
    k_srcdst1<<<BB*NN_, 256>>>(a_gat);
    k_attn<1><<<dim3(4, 4, BB), 256>>>(p_wh1, p_src1, p_dst1, p_adjm, p_multi, 256);
    k_mm<0><<<dim3(128, 2), 256>>>(p_multi, p_WgoT, nullptr, p_wh2, 8192, 128, 256);
    k_srcdst2<<<BB*NN_, 128>>>(a_go);
    k_attn<0><<<dim3(4, 2, BB), 256>>>(p_wh2, p_src2, p_dst2, p_adjm, p_x, 128);
    k_mm<1><<<dim3(128, 2), 256>>>(p_x, W_comp_w, W_comp_b, p_atoms_vec, 8192, 128, 128);
    k_mm<1><<<dim3(128, 2), 256>>>(p_atoms_vec, W_att_w, W_att_b, p_av_att, 8192, 128, 128);
    k_mean_part<<<dim3(8, BB), 128>>>(p_av_att, atoms_mask, p_pp, p_pm, NN_);
    k_mean_fin<<<BB, 128>>>(p_pp, p_pm, p_comp);

    // ---- join + head ----
    cudaStreamWaitEvent(0, evJ, 0);
    k_final<<<BB, 256>>>(pred_w, pred_b, out);
}

// round 10
// speedup vs baseline: 1.4687x; 1.0770x over previous
#include <cuda_runtime.h>
#include <cuda_bf16.h>
#include <cuda_fp16.h>
#include <math.h>
#include <stdint.h>

// ---------------- constants ----------------
#define BB   16
#define NN_  512
#define LL   1024
#define CD   128
#define GD   64
#define NH   4
#define LAT  128

// ---------------- scratch ----------------
__device__ float g_av       [BB*NN_*CD];
__device__ float g_wh1      [BB*NN_*(GD*NH)];
__device__ float g_multi    [BB*NN_*(GD*NH)];
__device__ float g_wh2      [BB*NN_*CD];
__device__ float g_x        [BB*NN_*CD];
__device__ float g_atoms_vec[BB*NN_*LAT];
__device__ float g_av_att   [BB*NN_*LAT];
__device__ float g_src1[BB*NH*NN_], g_dst1[BB*NH*NN_];
__device__ float g_src2[BB*NN_],    g_dst2[BB*NN_];
__device__ float g_cnvA[BB*LL*CD];
__device__ float g_cnvB[BB*LL*CD];
__device__ float g_T[30*11*CD];
__device__ float g_WcatT[256*128];
__device__ float g_WgoT [128*256];
__device__ float g_comp[BB*LAT], g_prot[BB*LAT];
__device__ float g_pp [BB*8*128];
__device__ float g_pm [BB*8];
__device__ float g_pp2[BB*8*128];
__device__ float g_pm2[BB*8];
__device__ uint32_t g_adjmask[BB*NN_*16];

__device__ __forceinline__ float lrelu(float x){ return x > 0.f ? x : 0.2f*x; }
__device__ __forceinline__ float eluf (float x){ return x > 0.f ? x : (__expf(x) - 1.f); }

// ---------------- f32x2 packed helpers (conv) ----------------
__device__ __forceinline__ uint64_t pk2(float x){
    uint32_t xi = __float_as_uint(x);
    uint64_t r; asm("mov.b64 %0, {%1, %1};" : "=l"(r) : "r"(xi)); return r;
}
__device__ __forceinline__ uint64_t pk2f(float x, float y){
    uint32_t xi = __float_as_uint(x), yi = __float_as_uint(y);
    uint64_t r; asm("mov.b64 %0, {%1, %2};" : "=l"(r) : "r"(xi), "r"(yi)); return r;
}
__device__ __forceinline__ void fma2(uint64_t& d, uint64_t a, uint64_t b){
    asm("fma.rn.f32x2 %0, %1, %2, %0;" : "+l"(d) : "l"(a), "l"(b));
}
__device__ __forceinline__ float2 up2(uint64_t v){
    uint32_t lo, hi; asm("mov.b64 {%0, %1}, %2;" : "=r"(lo), "=r"(hi) : "l"(v));
    return make_float2(__uint_as_float(lo), __uint_as_float(hi));
}

// ---------------- bf16 helpers (k_mm) ----------------
__device__ __forceinline__ void split2(float x, float y, uint32_t& hi, uint32_t& lo){
    __nv_bfloat162 h = __floats2bfloat162_rn(x, y);
    float hx = __bfloat162float(h.x), hy = __bfloat162float(h.y);
    __nv_bfloat162 l = __floats2bfloat162_rn(x - hx, y - hy);
    hi = *(uint32_t*)&h; lo = *(uint32_t*)&l;
}
__device__ __forceinline__ void mma16816(float* d, const uint32_t* a, const uint32_t* b){
    asm volatile(
        "mma.sync.aligned.m16n8k16.row.col.f32.bf16.bf16.f32 "
        "{%0,%1,%2,%3},{%4,%5,%6,%7},{%8,%9},{%0,%1,%2,%3};"
        : "+f"(d[0]), "+f"(d[1]), "+f"(d[2]), "+f"(d[3])
        : "r"(a[0]), "r"(a[1]), "r"(a[2]), "r"(a[3]), "r"(b[0]), "r"(b[1]));
}

// ---------------- fp16 helpers (attention) ----------------
__device__ __forceinline__ uint32_t packhf2(float x, float y){
    __half2 h = __floats2half2_rn(x, y);
    return *(uint32_t*)&h;
}
__device__ __forceinline__ uint32_t hadd2uh(uint32_t a, uint32_t b){
    __half2 r = __hadd2(*(__half2*)&a, *(__half2*)&b);
    return *(uint32_t*)&r;
}
__device__ __forceinline__ uint32_t hmul2uh(uint32_t a, uint32_t b){
    __half2 r = __hmul2(*(__half2*)&a, *(__half2*)&b);
    return *(uint32_t*)&r;
}
__device__ __forceinline__ float2 h2f2(uint32_t w){
    return __half22float2(*(__half2*)&w);
}
__device__ __forceinline__ void mma16816h(float* d, const uint32_t* a, const uint32_t* b){
    asm volatile(
        "mma.sync.aligned.m16n8k16.row.col.f32.f16.f16.f32 "
        "{%0,%1,%2,%3},{%4,%5,%6,%7},{%8,%9},{%0,%1,%2,%3};"
        : "+f"(d[0]), "+f"(d[1]), "+f"(d[2]), "+f"(d[3])
        : "r"(a[0]), "r"(a[1]), "r"(a[2]), "r"(a[3]), "r"(b[0]), "r"(b[1]));
}

// ---------------- fused prep kernel ----------------
__global__ void __launch_bounds__(256) k_prep(
    const int* __restrict__ adj, const float* __restrict__ W_gat,
    const float* __restrict__ W_go, const float* __restrict__ conv_w,
    const float* __restrict__ E_amino, const int* __restrict__ atoms,
    const float* __restrict__ E_atom)
{
    const int bid = blockIdx.x, tid = threadIdx.x;
    if (bid < 16384) {
        int t = bid*256 + tid;
        uint32_t bal = __ballot_sync(0xffffffffu, adj[t] > 0);
        if ((t & 31) == 0) g_adjmask[t >> 5] = bal;
    } else if (bid < 16512) {
        int idx = (bid - 16384)*256 + tid;
        int n = idx >> 7, k = idx & 127;
        int h = n >> 6, f = n & 63;
        g_WcatT[n*128 + k] = W_gat[((h*128) + k)*64 + f];
    } else if (bid < 16640) {
        int idx = (bid - 16512)*256 + tid;
        int n = idx >> 8, k = idx & 255;
        g_WgoT[n*256 + k] = W_go[k*128 + n];
    } else if (bid < 16805) {
        int idx = (bid - 16640)*256 + tid;
        if (idx < 42240) {
            int f = idx & 127, rest = idx >> 7;
            int dl = rest % 11, a = rest / 11;
            float acc = 0.f;
            #pragma unroll
            for (int df = 0; df < 11; ++df) {
                int fi = f + df - 5;
                if (fi >= 0 && fi < 128) acc += conv_w[dl*11 + df] * E_amino[a*128 + fi];
            }
            g_T[(a*11 + dl)*128 + f] = acc;
        }
    } else {
        int idx = (bid - 16805)*256 + tid;
        int row = idx >> 7, f = idx & 127;
        g_av[(size_t)row*128 + f] = E_atom[atoms[row]*128 + f];
    }
}

// ---------------- bf16-split tensor GEMM (64x64 tiles) ----------------
template<int ACT>
__global__ void __launch_bounds__(256) k_mm(
    const float* __restrict__ A, const float* __restrict__ BT,
    const float* __restrict__ bias, float* __restrict__ C,
    int M, int N, int K)
{
    __shared__ uint32_t Ah[2304], Al[2304], Bh[2304], Bl[2304];

    const int m0 = blockIdx.x*64, n0 = blockIdx.y*64;
    const int tid = threadIdx.x, w = tid >> 5, lane = tid & 31;
    const int wm = w & 3, wn = w >> 2;
    const int r4 = lane >> 2, cl = lane & 3;

    float acc[4][4];
    #pragma unroll
    for (int j = 0; j < 4; ++j)
        #pragma unroll
        for (int q = 0; q < 4; ++q) acc[j][q] = 0.f;

    for (int k0 = 0; k0 < K; k0 += 64) {
        __syncthreads();
        #pragma unroll
        for (int s = tid; s < 1024; s += 256) {
            int r = s >> 4, q = s & 15;
            float4 v = *(const float4*)&A[(size_t)(m0+r)*K + k0 + q*4];
            uint32_t h0,l0,h1,l1;
            split2(v.x, v.y, h0, l0); split2(v.z, v.w, h1, l1);
            int off = r*36 + q*2;
            Ah[off] = h0; Ah[off+1] = h1;
            Al[off] = l0; Al[off+1] = l1;
            float4 bv = *(const float4*)&BT[(size_t)(n0+r)*K + k0 + q*4];
            split2(bv.x, bv.y, h0, l0); split2(bv.z, bv.w, h1, l1);
            Bh[off] = h0; Bh[off+1] = h1;
            Bl[off] = l0; Bl[off+1] = l1;
        }
        __syncthreads();
        #pragma unroll
        for (int kk = 0; kk < 4; ++kk) {
            const int kw = kk*8;
            uint32_t ah[4], al[4];
            {
                int base = (wm*16 + r4)*36 + kw + cl;
                ah[0]=Ah[base];     ah[1]=Ah[base+288];
                ah[2]=Ah[base+4];   ah[3]=Ah[base+292];
                al[0]=Al[base];     al[1]=Al[base+288];
                al[2]=Al[base+4];   al[3]=Al[base+292];
            }
            uint32_t bh[4][2], bl[4][2];
            #pragma unroll
            for (int fn = 0; fn < 4; ++fn) {
                int base = (wn*32 + fn*8 + r4)*36 + kw + cl;
                bh[fn][0]=Bh[base]; bh[fn][1]=Bh[base+4];
                bl[fn][0]=Bl[base]; bl[fn][1]=Bl[base+4];
            }
            #pragma unroll
            for (int fn = 0; fn < 4; ++fn) {
                mma16816(acc[fn], ah, bh[fn]);
                mma16816(acc[fn], ah, bl[fn]);
                mma16816(acc[fn], al, bh[fn]);
            }
        }
    }
    #pragma unroll
    for (int fn = 0; fn < 4; ++fn) {
        int row = m0 + wm*16 + r4;
        int col = n0 + wn*32 + fn*8 + 2*cl;
        float b0 = 0.f, b1 = 0.f;
        if (bias) { b0 = bias[col]; b1 = bias[col+1]; }
        float v0 = acc[fn][0] + b0, v1 = acc[fn][1] + b1;
        float v2 = acc[fn][2] + b0, v3 = acc[fn][3] + b1;
        if (ACT) { v0=lrelu(v0); v1=lrelu(v1); v2=lrelu(v2); v3=lrelu(v3); }
        *(float2*)&C[(size_t)row*N + col]     = make_float2(v0, v1);
        *(float2*)&C[(size_t)(row+8)*N + col] = make_float2(v2, v3);
    }
}

// ---------------- GAT attention: fp16, 128-row i-tile, 64-col f-tile, 512 threads ----------------
template<int MH>
__global__ void __launch_bounds__(512) k_attn(
    const float* __restrict__ wh, const float* __restrict__ src,
    const float* __restrict__ dst, const uint32_t* __restrict__ adjmask,
    float* __restrict__ out, int WS)
{
    __shared__ uint32_t Dp[256];     // fp16x2 (d_{2j}, d_{2j+1})
    __shared__ uint32_t PQ[512];     // fp16x2 (e^{d_j}, e^{0.2 d_j})
    __shared__ uint32_t sD2[128];    // fp16x2 (s_i, s_i)
    __shared__ uint32_t sPQ[128];    // fp16x2 (e^{s_i}, e^{0.2 s_i})
    __shared__ float Sum[128], pst[512];
    __shared__ uint32_t msk[2048];
    __shared__ uint32_t Ath[2304];   // 128 rows * 18 words
    __shared__ uint32_t Bh[1152], Bl[1152];  // 64 f * 18 words

    const int it = blockIdx.x, hy = blockIdx.y, b = blockIdx.z;
    const int i0 = it*128;
    const int tid = threadIdx.x, w = tid >> 5, lane = tid & 31;
    const int r4 = lane >> 2, cl = lane & 3;
    const int whoff = hy*64;
    const int sdoff = MH ? (b*NH + hy) : b;

    const float* dstb = dst + (size_t)sdoff*512;
    const float* srcb = src + (size_t)sdoff*512;
    if (tid < 256) {
        float d0 = dstb[2*tid], d1 = dstb[2*tid + 1];
        Dp[tid] = packhf2(d0, d1);
        PQ[2*tid]     = packhf2(__expf(d0), __expf(0.2f*d0));
        PQ[2*tid + 1] = packhf2(__expf(d1), __expf(0.2f*d1));
    }
    if (tid < 128) {
        float s = srcb[i0 + tid];
        sD2[tid] = packhf2(s, s);
        sPQ[tid] = packhf2(__expf(s), __expf(0.2f*s));
    }
    {
        const uint32_t* mb = adjmask + ((size_t)(b*512) + i0)*16;
        for (int s = tid; s < 2048; s += 512) msk[s] = mb[s];
    }

    const int wm = w & 3, wn = w >> 2;     // 4 m-warps x 4 n-warps
    float acc[2][2][4];
    #pragma unroll
    for (int i = 0; i < 2; ++i)
        #pragma unroll
        for (int j = 0; j < 2; ++j)
            #pragma unroll
            for (int q = 0; q < 4; ++q) acc[i][j][q] = 0.f;

    const int ai = tid >> 2, qt = tid & 3;   // row, j-quarter (4 pairs each)
    __syncthreads();
    const uint32_t si2 = sD2[ai], piq = sPQ[ai];
    float ps = 0.f;

    for (int c = 0; c < 16; ++c) {
        const int j0 = c*32;
        if (c) __syncthreads();
        // --- A tile build (128 x 32), fp16 packed pipeline (4 pairs/thread) ---
        {
            uint32_t mw = msk[ai*16 + c];
            #pragma unroll
            for (int jp = 0; jp < 4; ++jp) {
                int jl0 = qt*8 + jp*2, jl1 = jl0 + 1;
                uint32_t s2 = hadd2uh(si2, Dp[c*16 + qt*4 + jp]);
                uint32_t pr0 = hmul2uh(PQ[j0 + jl0], piq);
                uint32_t pr1 = hmul2uh(PQ[j0 + jl1], piq);
                uint32_t u0 = (s2 & 0x8000u)     ? (pr0 >> 16)          : (pr0 & 0xffffu);
                uint32_t u1 = (s2 & 0x80000000u) ? (pr1 & 0xffff0000u)  : (pr1 << 16);
                if (!((mw >> jl0) & 1u)) u0 = 0;
                if (!((mw >> jl1) & 1u)) u1 = 0;
                uint32_t word = u0 | u1;
                Ath[ai*18 + qt*4 + jp] = word;
                float2 f = h2f2(word);
                ps += f.x + f.y;
            }
        }
        // --- B tile build: WhT [64 f x 32 j] fp16 hi/lo (2 pairs/thread) ---
        {
            const int f = tid & 63, jg = tid >> 6;   // 8 j-groups of 4
            #pragma unroll
            for (int p = 0; p < 2; ++p) {
                int jl = jg*4 + p*2;
                float v0 = wh[(size_t)(b*512 + j0 + jl)*WS + whoff + f];
                float v1 = wh[(size_t)(b*512 + j0 + jl + 1)*WS + whoff + f];
                uint32_t hw = packhf2(v0, v1);
                float2 hv = h2f2(hw);
                uint32_t lw = packhf2(v0 - hv.x, v1 - hv.y);
                Bh[f*18 + jg*2 + p] = hw;
                Bl[f*18 + jg*2 + p] = lw;
            }
        }
        __syncthreads();
        // --- MMA: 2 k-steps of 16 ---
        #pragma unroll
        for (int kk = 0; kk < 2; ++kk) {
            const int kw = kk*8;
            uint32_t ah[2][4];
            #pragma unroll
            for (int fm = 0; fm < 2; ++fm) {
                int base = (wm*32 + fm*16 + r4)*18 + kw + cl;
                ah[fm][0]=Ath[base];     ah[fm][1]=Ath[base+144];
                ah[fm][2]=Ath[base+4];   ah[fm][3]=Ath[base+148];
            }
            uint32_t bh[2][2], bl[2][2];
            #pragma unroll
            for (int fn = 0; fn < 2; ++fn) {
                int base = (wn*16 + fn*8 + r4)*18 + kw + cl;
                bh[fn][0]=Bh[base]; bh[fn][1]=Bh[base+4];
                bl[fn][0]=Bl[base]; bl[fn][1]=Bl[base+4];
            }
            #pragma unroll
            for (int fm = 0; fm < 2; ++fm)
                #pragma unroll
                for (int fn = 0; fn < 2; ++fn) {
                    mma16816h(acc[fm][fn], ah[fm], bh[fn]);
                    mma16816h(acc[fm][fn], ah[fm], bl[fn]);
                }
        }
    }
    pst[tid] = ps;
    __syncthreads();
    if (tid < 128)
        Sum[tid] = pst[4*tid] + pst[4*tid+1] + pst[4*tid+2] + pst[4*tid+3];
    __syncthreads();
    // --- epilogue: normalize + elu ---
    #pragma unroll
    for (int fm = 0; fm < 2; ++fm) {
        int rl = wm*32 + fm*16 + r4;
        float S0 = Sum[rl],   i0v = (S0 > 0.f) ? 1.f/S0 : 0.f;
        float S1 = Sum[rl+8], i1v = (S1 > 0.f) ? 1.f/S1 : 0.f;
        #pragma unroll
        for (int fn = 0; fn < 2; ++fn) {
            int col = whoff + wn*16 + fn*8 + 2*cl;
            float v0 = eluf(acc[fm][fn][0] * i0v);
            float v1 = eluf(acc[fm][fn][1] * i0v);
            float v2 = eluf(acc[fm][fn][2] * i1v);
            float v3 = eluf(acc[fm][fn][3] * i1v);
            *(float2*)&out[(size_t)(b*512 + i0 + rl)*WS + col]     = make_float2(v0, v1);
            *(float2*)&out[(size_t)(b*512 + i0 + rl + 8)*WS + col] = make_float2(v2, v3);
        }
    }
}

// ---------------- src/dst score kernels ----------------
__global__ void k_srcdst1(const float* __restrict__ a_gat){
    const int row = blockIdx.x;
    const int b = row >> 9, n = row & 511;
    const int tid = threadIdx.x;
    __shared__ float wrow[256];
    wrow[tid] = g_wh1[(size_t)row*256 + tid];
    __syncthreads();
    const int w = tid >> 5, l = tid & 31;
    const int h = w >> 1, half = w & 1;
    float v = wrow[h*64 + l]      * a_gat[h*128 + half*64 + l]
            + wrow[h*64 + 32 + l] * a_gat[h*128 + half*64 + 32 + l];
    #pragma unroll
    for (int o = 16; o; o >>= 1) v += __shfl_down_sync(0xffffffffu, v, o);
    if (l == 0) {
        float* outp = half ? g_dst1 : g_src1;
        outp[(size_t)(b*4 + h)*512 + n] = v;
    }
}
__global__ void k_srcdst2(const float* __restrict__ a_go){
    const int row = blockIdx.x;
    const int tid = threadIdx.x;
    __shared__ float wrow[128];
    __shared__ float part[4];
    wrow[tid] = g_wh2[(size_t)row*128 + tid];
    __syncthreads();
    const int w = tid >> 5, l = tid & 31;
    const int which = w >> 1, p = w & 1;
    float v = wrow[p*64 + l]      * a_go[which*128 + p*64 + l]
            + wrow[p*64 + 32 + l] * a_go[which*128 + p*64 + 32 + l];
    #pragma unroll
    for (int o = 16; o; o >>= 1) v += __shfl_down_sync(0xffffffffu, v, o);
    if (l == 0) part[w] = v;
    __syncthreads();
    if (tid == 0) g_src2[row] = part[0] + part[1];
    if (tid == 1) g_dst2[row] = part[2] + part[3];
}

// ---------------- CNN ----------------
__global__ void k_conv1(const int* __restrict__ amino, const float* __restrict__ conv_b){
    const int l = blockIdx.x, b = blockIdx.y, f = threadIdx.x;
    float acc = conv_b[0];
    #pragma unroll
    for (int dl = 0; dl < 11; ++dl) {
        int l2 = l + dl - 5;
        if (l2 >= 0 && l2 < 1024) {
            int id = amino[b*1024 + l2];
            acc += g_T[((size_t)id*11 + dl)*128 + f];
        }
    }
    g_cnvA[((size_t)(b*1024) + l)*128 + f] = fmaxf(acc, 0.f);
}

// 11x11 SAME conv; sliding l-window: thread owns 2 consecutive rows, 1 new row per dl.
// block covers 16 l x 128 f; tile 26 rows x 140 pitch (data at col f+5).
#define CONV_LOADROW(dstarr, trow) do {                                        \
    const float* _s = &tile[(trow)*140 + f0];                                  \
    _Pragma("unroll")                                                          \
    for (int _q = 0; _q < 4; ++_q) {                                           \
        float4 _v = *(const float4*)&_s[_q*4];                                 \
        dstarr[_q*4+0]=_v.x; dstarr[_q*4+1]=_v.y;                              \
        dstarr[_q*4+2]=_v.z; dstarr[_q*4+3]=_v.w;                              \
    }                                                                          \
} while(0)

#define CONV_STEP(Aarr, Barr, dl_) do {                                        \
    uint64_t vp[14];                                                           \
    _Pragma("unroll")                                                          \
    for (int _j = 0; _j < 14; ++_j) vp[_j] = pk2f(Aarr[_j], Barr[_j]);         \
    const float* _w = ws + (dl_)*11;                                           \
    _Pragma("unroll")                                                          \
    for (int _df = 0; _df < 11; ++_df) {                                       \
        uint64_t _wv = pk2(_w[_df]);                                           \
        fma2(acc[0], _wv, vp[_df+0]);                                          \
        fma2(acc[1], _wv, vp[_df+1]);                                          \
        fma2(acc[2], _wv, vp[_df+2]);                                          \
        fma2(acc[3], _wv, vp[_df+3]);                                          \
    }                                                                          \
} while(0)

__global__ void __launch_bounds__(256) k_conv(
    const float* __restrict__ in, float* __restrict__ out,
    const float* __restrict__ wsrc, const float* __restrict__ bsrc)
{
    __shared__ float tile[26*140];
    __shared__ float ws[121];
    const int lb = blockIdx.x * 16, b = blockIdx.y;
    const int tid = threadIdx.x;
    if (tid < 121) ws[tid] = wsrc[tid];
    // tile: row r <-> gl = lb + r - 5; input f at col f+5; zero borders
    for (int idx = tid; idx < 832; idx += 256) {          // 26 rows * 32 float4
        int r = idx >> 5, c4 = idx & 31;
        int gl = lb + r - 5;
        float4 v = make_float4(0.f, 0.f, 0.f, 0.f);
        if (gl >= 0 && gl < 1024)
            v = *(const float4*)&in[((size_t)(b*1024) + gl)*128 + c4*4];
        float* t = &tile[r*140 + 5 + c4*4];
        t[0]=v.x; t[1]=v.y; t[2]=v.z; t[3]=v.w;
    }
    for (int idx = tid; idx < 312; idx += 256) {          // 26 rows * 12 border cols
        int r = idx / 12, c = idx % 12;
        tile[r*140 + (c < 5 ? c : 128 + c)] = 0.f;        // cols 0..4 and 133..139
    }
    __syncthreads();

    const int fg = tid >> 3, lg = tid & 7;
    const int f0 = fg * 4;
    const int rbase = lg * 2;          // output rows lb+rbase, lb+rbase+1

    float r0[16], r1[16];
    CONV_LOADROW(r0, rbase);
    CONV_LOADROW(r1, rbase + 1);

    uint64_t acc[4];
    {
        uint64_t bp = pk2(bsrc[0]);
        acc[0]=bp; acc[1]=bp; acc[2]=bp; acc[3]=bp;
    }
    #pragma unroll
    for (int dl = 0; dl < 11; ++dl) {
        if ((dl & 1) == 0) {
            CONV_STEP(r0, r1, dl);
            if (dl < 10) CONV_LOADROW(r0, rbase + dl + 2);
        } else {
            CONV_STEP(r1, r0, dl);
            if (dl < 10) CONV_LOADROW(r1, rbase + dl + 2);
        }
    }
    float* o0 = out + ((size_t)(b*1024) + lb + rbase)*128 + f0;
    float* o1 = o0 + 128;
    #pragma unroll
    for (int k = 0; k < 4; ++k) {
        float2 v = up2(acc[k]);
        o0[k] = fmaxf(v.x, 0.f);
        o1[k] = fmaxf(v.y, 0.f);
    }
}

// ---------------- masked mean pooling ----------------
__global__ void k_mean_part(const float* __restrict__ in, const float* __restrict__ mask,
                            float* __restrict__ pp, float* __restrict__ pm, int NNd){
    const int ch = blockIdx.x, b = blockIdx.y, f = threadIdx.x;
    const int rows = NNd / 8;
    const int r0 = ch * rows;
    float s = 0.f, m = 0.f;
    #pragma unroll 4
    for (int n = r0; n < r0 + rows; ++n) {
        float mk = mask[b*NNd + n];
        m += mk;
        s += mk * in[((size_t)b*NNd + n)*128 + f];
    }
    pp[(size_t)(b*8 + ch)*128 + f] = s;
    if (f == 0) pm[b*8 + ch] = m;
}
__global__ void k_mean_fin(const float* __restrict__ pp, const float* __restrict__ pm,
                           float* __restrict__ outp){
    const int b = blockIdx.x, f = threadIdx.x;
    float s = 0.f, m = 0.f;
    #pragma unroll
    for (int ch = 0; ch < 8; ++ch) {
        s += pp[(size_t)(b*8 + ch)*128 + f];
        m += pm[b*8 + ch];
    }
    outp[b*128 + f] = s / m;
}

// ---------------- final predictor ----------------
__global__ void k_final(const float* __restrict__ pred_w, const float* __restrict__ pred_b,
                        float* __restrict__ out){
    __shared__ float red[256];
    const int b = blockIdx.x, c = threadIdx.x;
    float v = (c < 128) ? g_comp[b*128 + c] : g_prot[b*128 + (c - 128)];
    v = v > 0.f ? v : 0.04f*v;
    red[c] = v * pred_w[c];
    __syncthreads();
    for (int s = 128; s > 0; s >>= 1) {
        if (c < s) red[c] += red[c + s];
        __syncthreads();
    }
    if (c == 0) out[b] = red[0] + pred_b[0];
}

// ---------------- launch ----------------
extern "C" void kernel_launch(void* const* d_in, const int* in_sizes, int n_in,
                              void* d_out, int out_size)
{
    const int*   atoms      = (const int*)  d_in[0];
    const float* atoms_mask = (const float*)d_in[1];
    const int*   adj        = (const int*)  d_in[2];
    const int*   amino      = (const int*)  d_in[3];
    const float* amino_mask = (const float*)d_in[4];
    const float* E_atom     = (const float*)d_in[5];
    const float* E_amino    = (const float*)d_in[6];
    const float* W_gat      = (const float*)d_in[7];
    const float* a_gat      = (const float*)d_in[8];
    const float* W_go       = (const float*)d_in[9];
    const float* a_go       = (const float*)d_in[10];
    const float* W_comp_w   = (const float*)d_in[11];
    const float* W_comp_b   = (const float*)d_in[12];
    const float* conv_w     = (const float*)d_in[13];
    const float* conv_b     = (const float*)d_in[14];
    const float* W_att_w    = (const float*)d_in[15];
    const float* W_att_b    = (const float*)d_in[16];
    const float* pred_w     = (const float*)d_in[17];
    const float* pred_b     = (const float*)d_in[18];
    float* out = (float*)d_out;

    float *p_WcatT, *p_WgoT;
    float *p_av, *p_wh1, *p_multi, *p_wh2, *p_x, *p_atoms_vec, *p_av_att;
    float *p_src1, *p_dst1, *p_src2, *p_dst2, *p_cnvA, *p_cnvB, *p_comp, *p_prot;
    float *p_pp, *p_pm, *p_pp2, *p_pm2;
    uint32_t* p_adjm;
    cudaGetSymbolAddress((void**)&p_WcatT, g_WcatT);
    cudaGetSymbolAddress((void**)&p_WgoT,  g_WgoT);
    cudaGetSymbolAddress((void**)&p_av,    g_av);
    cudaGetSymbolAddress((void**)&p_wh1,   g_wh1);
    cudaGetSymbolAddress((void**)&p_multi, g_multi);
    cudaGetSymbolAddress((void**)&p_wh2,   g_wh2);
    cudaGetSymbolAddress((void**)&p_x,     g_x);
    cudaGetSymbolAddress((void**)&p_atoms_vec, g_atoms_vec);
    cudaGetSymbolAddress((void**)&p_av_att, g_av_att);
    cudaGetSymbolAddress((void**)&p_src1,  g_src1);
    cudaGetSymbolAddress((void**)&p_dst1,  g_dst1);
    cudaGetSymbolAddress((void**)&p_src2,  g_src2);
    cudaGetSymbolAddress((void**)&p_dst2,  g_dst2);
    cudaGetSymbolAddress((void**)&p_cnvA,  g_cnvA);
    cudaGetSymbolAddress((void**)&p_cnvB,  g_cnvB);
    cudaGetSymbolAddress((void**)&p_comp,  g_comp);
    cudaGetSymbolAddress((void**)&p_prot,  g_prot);
    cudaGetSymbolAddress((void**)&p_pp,    g_pp);
    cudaGetSymbolAddress((void**)&p_pm,    g_pm);
    cudaGetSymbolAddress((void**)&p_pp2,   g_pp2);
    cudaGetSymbolAddress((void**)&p_pm2,   g_pm2);
    cudaGetSymbolAddress((void**)&p_adjm,  g_adjmask);

    // stream fork for the independent protein branch
    cudaStream_t s2;
    cudaStreamCreateWithFlags(&s2, cudaStreamNonBlocking);
    cudaEvent_t evF, evJ;
    cudaEventCreateWithFlags(&evF, cudaEventDisableTiming);
    cudaEventCreateWithFlags(&evJ, cudaEventDisableTiming);

    // fused prep (both branches depend on it)
    k_prep<<<20901, 256>>>(adj, W_gat, W_go, conv_w, E_amino, atoms, E_atom);
    cudaEventRecord(evF, 0);
    cudaStreamWaitEvent(s2, evF, 0);

    // ---- protein branch (stream s2) ----
    k_conv1<<<dim3(LL, BB), 128, 0, s2>>>(amino, conv_b);
    k_conv<<<dim3(64, BB), 256, 0, s2>>>(p_cnvA, p_cnvB, conv_w + 121,   conv_b + 1);
    k_conv<<<dim3(64, BB), 256, 0, s2>>>(p_cnvB, p_cnvA, conv_w + 2*121, conv_b + 2);
    k_mm<1><<<dim3(256, 2), 256, 0, s2>>>(p_cnvA, W_att_w, W_att_b, p_cnvB, 16384, 128, 128);
    k_mean_part<<<dim3(8, BB), 128, 0, s2>>>(p_cnvB, amino_mask, p_pp2, p_pm2, LL);
    k_mean_fin<<<BB, 128, 0, s2>>>(p_pp2, p_pm2, p_prot);
    cudaEventRecord(evJ, s2);

    // ---- compound branch (default stream, concurrent) ----
    k_mm<0><<<dim3(128, 4), 256>>>(p_av, p_WcatT, nullptr, p_wh1, 8192, 256, 128);
    k_srcdst1<<<BB*NN_, 256>>>(a_gat);
    k_attn<1><<<dim3(4, 4, BB), 512>>>(p_wh1, p_src1, p_dst1, p_adjm, p_multi, 256);
    k_mm<0><<<dim3(128, 2), 256>>>(p_multi, p_WgoT, nullptr, p_wh2, 8192, 128, 256);
    k_srcdst2<<<BB*NN_, 128>>>(a_go);
    k_attn<0><<<dim3(4, 2, BB), 512>>>(p_wh2, p_src2, p_dst2, p_adjm, p_x, 128);
    k_mm<1><<<dim3(128, 2), 256>>>(p_x, W_comp_w, W_comp_b, p_atoms_vec, 8192, 128, 128);
    k_mm<1><<<dim3(128, 2), 256>>>(p_atoms_vec, W_att_w, W_att_b, p_av_att, 8192, 128, 128);
    k_mean_part<<<dim3(8, BB), 128>>>(p_av_att, atoms_mask, p_pp, p_pm, NN_);
    k_mean_fin<<<BB, 128>>>(p_pp, p_pm, p_comp);

    // ---- join + head ----
    cudaStreamWaitEvent(0, evJ, 0);
    k_final<<<BB, 256>>>(pred_w, pred_b, out);
}